// round 5
// baseline (speedup 1.0000x reference)
#include <cuda_runtime.h>
#include <math.h>
#include <stdint.h>

#define BATCH 2
#define SEQ   2048
#define DM    1024
#define NH    16
#define DK    64

__device__ float g_Q[BATCH * NH * SEQ * DK];   // [b,h,s,d]
__device__ float g_K[BATCH * NH * SEQ * DK];   // [b,h,s,d]
__device__ float g_V[BATCH * NH * SEQ * DK];   // [b,h,s,d]
__device__ float g_O[BATCH * SEQ * DM];        // [b,s,h*d]

__device__ __forceinline__ float to_tf32(float x) {
    float r;
    asm("cvt.rna.tf32.f32 %0, %1;" : "=f"(r) : "f"(x));
    return r;
}

__device__ __forceinline__ void mma_tf32(
    float& d0, float& d1, float& d2, float& d3,
    uint32_t a0, uint32_t a1, uint32_t a2, uint32_t a3,
    uint32_t b0, uint32_t b1)
{
    asm volatile(
        "mma.sync.aligned.m16n8k8.row.col.f32.tf32.tf32.f32 "
        "{%0,%1,%2,%3}, {%4,%5,%6,%7}, {%8,%9}, {%0,%1,%2,%3};\n"
        : "+f"(d0), "+f"(d1), "+f"(d2), "+f"(d3)
        : "r"(a0), "r"(a1), "r"(a2), "r"(a3), "r"(b0), "r"(b1));
}

__device__ __forceinline__ void cp16(float* dst, const float* src) {
    uint32_t d = (uint32_t)__cvta_generic_to_shared(dst);
    asm volatile("cp.async.cg.shared.global [%0], [%1], 16;\n" :: "r"(d), "l"(src));
}
#define CP_COMMIT() asm volatile("cp.async.commit_group;\n" ::: "memory")
#define CP_WAIT1()  asm volatile("cp.async.wait_group 1;\n" ::: "memory")

// ---------------- tf32 MMA GEMM: 128x128x16 tiles, cp.async 3-stage ---------
#define TBM 128
#define TBN 128
#define TBK 16
#define APAD 20
#define BPAD 136
#define STAGES 3

__global__ __launch_bounds__(256) void gemm_tf32_kernel(
    const float* __restrict__ Ain,
    const float* __restrict__ W0,
    const float* __restrict__ W1,
    const float* __restrict__ W2,
    float* __restrict__ out,
    int mode)
{
    __shared__ float As[STAGES][TBM * APAD];   // [m][k], stride APAD
    __shared__ float Bs[STAGES][TBK * BPAD];   // [k][n], stride BPAD

    const float* __restrict__ A = (mode == 1) ? (const float*)g_O : Ain;

    const int z = blockIdx.z;
    const float* __restrict__ W = (z == 0) ? W0 : (z == 1) ? W1 : W2;
    float* __restrict__ dstz = (mode == 1) ? out : (z == 0) ? g_Q : (z == 1) ? g_K : g_V;

    const int m0 = blockIdx.y * TBM;
    const int n0 = blockIdx.x * TBN;
    const int tid  = threadIdx.x;
    const int lane = tid & 31;
    const int wid  = tid >> 5;
    const int wm = wid >> 2;
    const int wn = wid & 3;
    const int lr = lane >> 2;
    const int lc = lane & 3;

    const int ar0 = tid >> 2;            // A loader: rows ar0, ar0+64
    const int aq0 = tid & 3;             // float4 within k (0..3)
    const int br0 = tid >> 5;            // B loader: rows br0, br0+8
    const int bq0 = tid & 31;            // float4 within n (0..31)

    float acc[4][4][4];
    #pragma unroll
    for (int i = 0; i < 4; i++)
        #pragma unroll
        for (int j = 0; j < 4; j++)
            #pragma unroll
            for (int r = 0; r < 4; r++) acc[i][j][r] = 0.f;

    const int NT = DM / TBK;             // 64

    // issue loads for k-tile kt into stage st
    auto issue = [&](int kt, int st) {
        const int k0 = kt * TBK;
        #pragma unroll
        for (int i = 0; i < 2; i++)
            cp16(&As[st][(ar0 + i * 64) * APAD + aq0 * 4],
                 A + (size_t)(m0 + ar0 + i * 64) * DM + k0 + aq0 * 4);
        #pragma unroll
        for (int i = 0; i < 2; i++)
            cp16(&Bs[st][(br0 + i * 8) * BPAD + bq0 * 4],
                 W + (size_t)(k0 + br0 + i * 8) * DM + n0 + bq0 * 4);
        CP_COMMIT();
    };

    issue(0, 0);
    issue(1, 1);

    for (int kt = 0; kt < NT; kt++) {
        const int st = kt % STAGES;
        CP_WAIT1();
        __syncthreads();
        if (kt + 2 < NT) issue(kt + 2, (kt + 2) % STAGES);

        const float* as = &As[st][0];
        const float* bs = &Bs[st][0];
        #pragma unroll
        for (int ks = 0; ks < 2; ks++) {
            const int k0 = ks * 8;
            uint32_t af[4][4], bf[4][2];
            #pragma unroll
            for (int mf = 0; mf < 4; mf++) {
                const int r = wm * 64 + mf * 16 + lr;
                af[mf][0] = __float_as_uint(to_tf32(as[(r    ) * APAD + k0 + lc    ]));
                af[mf][1] = __float_as_uint(to_tf32(as[(r + 8) * APAD + k0 + lc    ]));
                af[mf][2] = __float_as_uint(to_tf32(as[(r    ) * APAD + k0 + lc + 4]));
                af[mf][3] = __float_as_uint(to_tf32(as[(r + 8) * APAD + k0 + lc + 4]));
            }
            #pragma unroll
            for (int nf = 0; nf < 4; nf++) {
                const int c = wn * 32 + nf * 8 + lr;
                bf[nf][0] = __float_as_uint(to_tf32(bs[(k0 + lc    ) * BPAD + c]));
                bf[nf][1] = __float_as_uint(to_tf32(bs[(k0 + lc + 4) * BPAD + c]));
            }
            #pragma unroll
            for (int mf = 0; mf < 4; mf++)
                #pragma unroll
                for (int nf = 0; nf < 4; nf++)
                    mma_tf32(acc[mf][nf][0], acc[mf][nf][1], acc[mf][nf][2], acc[mf][nf][3],
                             af[mf][0], af[mf][1], af[mf][2], af[mf][3],
                             bf[nf][0], bf[nf][1]);
        }
    }

    const int rb = m0 + wm * 64 + lr;
    const int cb = n0 + wn * 32 + 2 * lc;
    #pragma unroll
    for (int mf = 0; mf < 4; mf++) {
        #pragma unroll
        for (int nf = 0; nf < 4; nf++) {
            const int n = cb + nf * 8;
            #pragma unroll
            for (int half = 0; half < 2; half++) {
                const int m = rb + mf * 16 + half * 8;
                float2 v = make_float2(acc[mf][nf][half * 2], acc[mf][nf][half * 2 + 1]);
                if (mode == 1) {
                    *(float2*)(out + (size_t)m * DM + n) = v;
                } else {
                    const int b_ = m >> 11, s_ = m & (SEQ - 1);
                    const int h = n >> 6, d = n & 63;
                    *(float2*)(dstz + (((size_t)(b_ * NH + h)) * SEQ + s_) * DK + d) = v;
                }
            }
        }
    }
}

// ---------------- RoPE (unchanged) ------------------------------------------
__global__ void rope_kernel(const int* __restrict__ pos)
{
    const int NP = BATCH * NH * SEQ * (DK / 2);
    int idx = blockIdx.x * blockDim.x + threadIdx.x;
    if (idx >= NP) return;

    const int i  = idx & 31;
    const int s_ = (idx >> 5) & (SEQ - 1);
    const int bh = idx >> 16;
    const int b_ = bh >> 4;

    const int p = pos[b_ * SEQ + s_];
    const float e = (float)(2 * i) / 64.0f;
    const float invf = 1.0f / powf(10000.0f, e);
    const float ang = (float)p * invf;
    float sn, cs;
    sincosf(ang, &sn, &cs);

    const size_t base = (size_t)idx * 2;
    float qe = g_Q[base], qo = g_Q[base + 1];
    g_Q[base]     = qe * cs - qo * sn;
    g_Q[base + 1] = qe * sn + qo * cs;
    float ke = g_K[base], ko = g_K[base + 1];
    g_K[base]     = ke * cs - ko * sn;
    g_K[base + 1] = ke * sn + ko * cs;
}

// ---------------- tf32 MMA flash attention ----------------------------------
// CTA = 128 query rows, 8 warps x 16 rows. KV tile = 64. Causal.
#define FBM 128
#define FBN 64
#define KP  68
#define VP  72
#define PP  68
#define FLASH_SMEM ((64*KP + 64*VP + 128*PP) * 4)

__global__ __launch_bounds__(256) void flash_mma_kernel()
{
    extern __shared__ float fsm[];
    float* Ks = fsm;                    // [64][KP]
    float* Vs = fsm + 64 * KP;          // [64][VP]
    float* Ps = fsm + 64 * (KP + VP);   // [128][PP], warp w owns rows 16w..16w+15

    const int bh = blockIdx.y;
    const int m0 = ((int)gridDim.x - 1 - (int)blockIdx.x) * FBM;  // heavy blocks first
    const int tid  = threadIdx.x;
    const int lane = tid & 31;
    const int w    = tid >> 5;
    const int lr   = lane >> 2;
    const int lc   = lane & 3;

    const float* __restrict__ Qb = g_Q + (size_t)bh * SEQ * DK;
    const float* __restrict__ Kb = g_K + (size_t)bh * SEQ * DK;
    const float* __restrict__ Vb = g_V + (size_t)bh * SEQ * DK;

    // ---- stage Q (x 1/sqrt(64), tf32) through Ps, then to register frags ----
    #pragma unroll
    for (int it = 0; it < 8; it++) {
        const int idx = tid + it * 256;       // 0..2047
        const int row = idx >> 4, q = idx & 15;
        float4 v = *(const float4*)(Qb + (size_t)(m0 + row) * DK + q * 4);
        v.x = to_tf32(v.x * 0.125f); v.y = to_tf32(v.y * 0.125f);
        v.z = to_tf32(v.z * 0.125f); v.w = to_tf32(v.w * 0.125f);
        *(float4*)(Ps + row * PP + q * 4) = v;
    }
    __syncthreads();

    uint32_t qf[8][4];
    {
        const float* Pq = Ps + (w * 16) * PP;
        #pragma unroll
        for (int k = 0; k < 8; k++) {
            qf[k][0] = __float_as_uint(Pq[(lr    ) * PP + k * 8 + lc    ]);
            qf[k][1] = __float_as_uint(Pq[(lr + 8) * PP + k * 8 + lc    ]);
            qf[k][2] = __float_as_uint(Pq[(lr    ) * PP + k * 8 + lc + 4]);
            qf[k][3] = __float_as_uint(Pq[(lr + 8) * PP + k * 8 + lc + 4]);
        }
    }

    float o[8][4];
    #pragma unroll
    for (int n = 0; n < 8; n++)
        #pragma unroll
        for (int c = 0; c < 4; c++) o[n][c] = 0.f;
    float mrow0 = -1e30f, mrow1 = -1e30f, lrow0 = 0.f, lrow1 = 0.f;

    const int gr_lo = m0 + w * 16;              // first row this warp owns
    const int nt = m0 / FBN + 2;                // tiles cover cols 0 .. m0+127
    for (int t = 0; t < nt; t++) {
        const int j0 = t * FBN;
        __syncthreads();   // protect Ks/Vs/Ps reuse
        #pragma unroll
        for (int it = 0; it < 4; it++) {
            const int idx = tid + it * 256;     // 0..1023
            const int row = idx >> 4, q = idx & 15;
            float4 kv = *(const float4*)(Kb + (size_t)(j0 + row) * DK + q * 4);
            kv.x = to_tf32(kv.x); kv.y = to_tf32(kv.y);
            kv.z = to_tf32(kv.z); kv.w = to_tf32(kv.w);
            *(float4*)(Ks + row * KP + q * 4) = kv;
            float4 vv = *(const float4*)(Vb + (size_t)(j0 + row) * DK + q * 4);
            vv.x = to_tf32(vv.x); vv.y = to_tf32(vv.y);
            vv.z = to_tf32(vv.z); vv.w = to_tf32(vv.w);
            *(float4*)(Vs + row * VP + q * 4) = vv;
        }
        __syncthreads();

        // warps fully above the diagonal have nothing to do on this tile
        if (j0 > gr_lo + 15) continue;

        // ---- S = Q K^T (rows w*16..w*16+15, cols j0..j0+63) ----
        float s[8][4];
        #pragma unroll
        for (int n = 0; n < 8; n++)
            #pragma unroll
            for (int c = 0; c < 4; c++) s[n][c] = 0.f;

        #pragma unroll
        for (int k = 0; k < 8; k++) {
            #pragma unroll
            for (int n = 0; n < 8; n++) {
                const uint32_t b0 = __float_as_uint(Ks[(n * 8 + lr) * KP + k * 8 + lc    ]);
                const uint32_t b1 = __float_as_uint(Ks[(n * 8 + lr) * KP + k * 8 + lc + 4]);
                mma_tf32(s[n][0], s[n][1], s[n][2], s[n][3],
                         qf[k][0], qf[k][1], qf[k][2], qf[k][3], b0, b1);
            }
        }

        // ---- causal mask (only tiles crossing the diagonal) ----
        if (j0 + FBN - 1 > gr_lo) {
            const int r0 = gr_lo + lr;
            #pragma unroll
            for (int n = 0; n < 8; n++) {
                const int c0 = j0 + n * 8 + 2 * lc;
                if (c0     > r0)     s[n][0] = -1e30f;
                if (c0 + 1 > r0)     s[n][1] = -1e30f;
                if (c0     > r0 + 8) s[n][2] = -1e30f;
                if (c0 + 1 > r0 + 8) s[n][3] = -1e30f;
            }
        }

        // ---- online softmax (rows lr and lr+8) ----
        float mx0 = -1e30f, mx1 = -1e30f;
        #pragma unroll
        for (int n = 0; n < 8; n++) {
            mx0 = fmaxf(mx0, fmaxf(s[n][0], s[n][1]));
            mx1 = fmaxf(mx1, fmaxf(s[n][2], s[n][3]));
        }
        mx0 = fmaxf(mx0, __shfl_xor_sync(0xffffffffu, mx0, 1));
        mx0 = fmaxf(mx0, __shfl_xor_sync(0xffffffffu, mx0, 2));
        mx1 = fmaxf(mx1, __shfl_xor_sync(0xffffffffu, mx1, 1));
        mx1 = fmaxf(mx1, __shfl_xor_sync(0xffffffffu, mx1, 2));

        const float mn0 = fmaxf(mrow0, mx0);
        const float mn1 = fmaxf(mrow1, mx1);
        const float sc0 = __expf(mrow0 - mn0);
        const float sc1 = __expf(mrow1 - mn1);
        lrow0 *= sc0; lrow1 *= sc1;
        #pragma unroll
        for (int n = 0; n < 8; n++) {
            o[n][0] *= sc0; o[n][1] *= sc0;
            o[n][2] *= sc1; o[n][3] *= sc1;
        }
        mrow0 = mn0; mrow1 = mn1;

        float* Pw = Ps + (w * 16) * PP;
        #pragma unroll
        for (int n = 0; n < 8; n++) {
            const float p0 = __expf(s[n][0] - mn0);
            const float p1 = __expf(s[n][1] - mn0);
            const float p2 = __expf(s[n][2] - mn1);
            const float p3 = __expf(s[n][3] - mn1);
            lrow0 += p0 + p1;
            lrow1 += p2 + p3;
            *(float2*)(Pw + (lr    ) * PP + n * 8 + 2 * lc) = make_float2(to_tf32(p0), to_tf32(p1));
            *(float2*)(Pw + (lr + 8) * PP + n * 8 + 2 * lc) = make_float2(to_tf32(p2), to_tf32(p3));
        }
        __syncwarp();

        // ---- O += P V ----
        #pragma unroll
        for (int k = 0; k < 8; k++) {
            const uint32_t a0 = __float_as_uint(Pw[(lr    ) * PP + k * 8 + lc    ]);
            const uint32_t a1 = __float_as_uint(Pw[(lr + 8) * PP + k * 8 + lc    ]);
            const uint32_t a2 = __float_as_uint(Pw[(lr    ) * PP + k * 8 + lc + 4]);
            const uint32_t a3 = __float_as_uint(Pw[(lr + 8) * PP + k * 8 + lc + 4]);
            #pragma unroll
            for (int n = 0; n < 8; n++) {
                const uint32_t b0 = __float_as_uint(Vs[(k * 8 + lc    ) * VP + n * 8 + lr]);
                const uint32_t b1 = __float_as_uint(Vs[(k * 8 + lc + 4) * VP + n * 8 + lr]);
                mma_tf32(o[n][0], o[n][1], o[n][2], o[n][3], a0, a1, a2, a3, b0, b1);
            }
        }
    }

    // ---- finalize ----
    lrow0 += __shfl_xor_sync(0xffffffffu, lrow0, 1);
    lrow0 += __shfl_xor_sync(0xffffffffu, lrow0, 2);
    lrow1 += __shfl_xor_sync(0xffffffffu, lrow1, 1);
    lrow1 += __shfl_xor_sync(0xffffffffu, lrow1, 2);
    const float inv0 = 1.0f / lrow0;
    const float inv1 = 1.0f / lrow1;

    const int b_ = bh >> 4, h = bh & 15;
    const int r0 = m0 + w * 16 + lr;
    const int r1 = r0 + 8;
    #pragma unroll
    for (int n = 0; n < 8; n++) {
        const int d = h * 64 + n * 8 + 2 * lc;
        *(float2*)(g_O + ((size_t)b_ * SEQ + r0) * DM + d) =
            make_float2(o[n][0] * inv0, o[n][1] * inv0);
        *(float2*)(g_O + ((size_t)b_ * SEQ + r1) * DM + d) =
            make_float2(o[n][2] * inv1, o[n][3] * inv1);
    }
}

// ---------------- launch ----------------------------------------------------
extern "C" void kernel_launch(void* const* d_in, const int* in_sizes, int n_in,
                              void* d_out, int out_size)
{
    (void)in_sizes; (void)n_in; (void)out_size;
    const float* x   = (const float*)d_in[0];
    const int*   pos = (const int*)  d_in[1];
    const float* WQ  = (const float*)d_in[2];
    const float* WK  = (const float*)d_in[3];
    const float* WV  = (const float*)d_in[4];
    const float* WO  = (const float*)d_in[5];
    float* out = (float*)d_out;

    cudaFuncSetAttribute(flash_mma_kernel,
                         cudaFuncAttributeMaxDynamicSharedMemorySize, FLASH_SMEM);

    dim3 gq(DM / TBN, (BATCH * SEQ) / TBM, 3);
    gemm_tf32_kernel<<<gq, 256>>>(x, WQ, WK, WV, nullptr, 0);

    const int NP = BATCH * NH * SEQ * (DK / 2);
    rope_kernel<<<(NP + 255) / 256, 256>>>(pos);

    dim3 gf(SEQ / FBM, BATCH * NH);
    flash_mma_kernel<<<gf, 256, FLASH_SMEM>>>();

    dim3 go(DM / TBN, (BATCH * SEQ) / TBM, 1);
    gemm_tf32_kernel<<<go, 256>>>(nullptr, WO, nullptr, nullptr, out, 1);
}

// round 7
// speedup vs baseline: 1.6843x; 1.6843x over previous
#include <cuda_runtime.h>
#include <cuda_fp16.h>
#include <math.h>
#include <stdint.h>

#define BATCH 2
#define SEQ   2048
#define DM    1024
#define NH    16
#define DK    64

__device__ float g_Q[BATCH * NH * SEQ * DK];   // [b,h,s,d]
__device__ float g_K[BATCH * NH * SEQ * DK];   // [b,h,s,d]
__device__ float g_V[BATCH * NH * SEQ * DK];   // [b,h,s,d]
__device__ float g_O[BATCH * SEQ * DM];        // [b,s,h*d]

__device__ __forceinline__ uint32_t h2u(__half2 h) {
    return *reinterpret_cast<uint32_t*>(&h);
}
__device__ __forceinline__ uint32_t f2h2(float a, float b) {
    __half2 h = __floats2half2_rn(a, b);
    return *reinterpret_cast<uint32_t*>(&h);
}

// fp16 MMA, fp32 accumulate: D(16x8) += A(16x16) * B(16x8)
__device__ __forceinline__ void mma_f16(
    float& d0, float& d1, float& d2, float& d3,
    uint32_t a0, uint32_t a1, uint32_t a2, uint32_t a3,
    uint32_t b0, uint32_t b1)
{
    asm volatile(
        "mma.sync.aligned.m16n8k16.row.col.f32.f16.f16.f32 "
        "{%0,%1,%2,%3}, {%4,%5,%6,%7}, {%8,%9}, {%0,%1,%2,%3};\n"
        : "+f"(d0), "+f"(d1), "+f"(d2), "+f"(d3)
        : "r"(a0), "r"(a1), "r"(a2), "r"(a3), "r"(b0), "r"(b1));
}

// ---------------- fp16 MMA GEMM: 128x128x16 tiles, 8 warps (64x32 each) -----
#define TBM 128
#define TBN 128
#define TBK 16
#define APAD2 12    // As2 row stride in half2: banks 12*lr+lc distinct
#define BPAD2 136   // Bs2 row stride in half2: banks 8*lc+lr distinct

// mode 0: A=Ain(x), W by blockIdx.z (WQ/WK/WV), dst = g_Q/g_K/g_V [b,h,s,d]
// mode 1: A=g_O (resolved in kernel), W=W0, dst = out
__global__ __launch_bounds__(256) void gemm_f16_kernel(
    const float* __restrict__ Ain,
    const float* __restrict__ W0,
    const float* __restrict__ W1,
    const float* __restrict__ W2,
    float* __restrict__ out,
    int mode)
{
    __shared__ __half2 As2[2][TBM * APAD2];   // [m][k/2]
    __shared__ __half2 Bs2[2][(TBK / 2) * BPAD2];  // [k/2][n]

    const float* __restrict__ A = (mode == 1) ? (const float*)g_O : Ain;
    const int z = blockIdx.z;
    const float* __restrict__ W = (z == 0) ? W0 : (z == 1) ? W1 : W2;
    float* __restrict__ dstz = (mode == 1) ? out : (z == 0) ? g_Q : (z == 1) ? g_K : g_V;

    const int m0 = blockIdx.y * TBM;
    const int n0 = blockIdx.x * TBN;
    const int tid  = threadIdx.x;
    const int lane = tid & 31;
    const int wid  = tid >> 5;
    const int wm = wid >> 2;       // 0..1: 64-row slab
    const int wn = wid & 3;        // 0..3: 32-col slab
    const int lr = lane >> 2;
    const int lc = lane & 3;

    // loader coords
    const int arow = tid >> 2;      // A rows arow, arow+64 ; q = tid&3 float4
    const int aq   = tid & 3;
    const int bkp  = tid >> 5;      // B k-pair row 0..7
    const int bnq  = tid & 31;      // n float4 quad 0..31

    float acc[4][4][4];
    #pragma unroll
    for (int i = 0; i < 4; i++)
        #pragma unroll
        for (int j = 0; j < 4; j++)
            #pragma unroll
            for (int r = 0; r < 4; r++) acc[i][j][r] = 0.f;

    float4 la[2], lb[2];

    auto load_regs = [&](int kt) {
        const int k0 = kt * TBK;
        #pragma unroll
        for (int i = 0; i < 2; i++)
            la[i] = *(const float4*)(A + (size_t)(m0 + arow + i * 64) * DM + k0 + aq * 4);
        lb[0] = *(const float4*)(W + (size_t)(k0 + 2 * bkp    ) * DM + n0 + bnq * 4);
        lb[1] = *(const float4*)(W + (size_t)(k0 + 2 * bkp + 1) * DM + n0 + bnq * 4);
    };
    auto store_regs = [&](int buf) {
        #pragma unroll
        for (int i = 0; i < 2; i++) {
            As2[buf][(arow + i * 64) * APAD2 + aq * 2    ] = __floats2half2_rn(la[i].x, la[i].y);
            As2[buf][(arow + i * 64) * APAD2 + aq * 2 + 1] = __floats2half2_rn(la[i].z, la[i].w);
        }
        const float* f0 = (const float*)&lb[0];
        const float* f1 = (const float*)&lb[1];
        #pragma unroll
        for (int i = 0; i < 4; i++)
            Bs2[buf][bkp * BPAD2 + bnq * 4 + i] = __floats2half2_rn(f0[i], f1[i]);
    };

    load_regs(0);
    store_regs(0);
    __syncthreads();

    const int NT = DM / TBK;   // 64
    for (int kt = 0; kt < NT; kt++) {
        const int buf = kt & 1;
        const bool more = (kt + 1 < NT);
        if (more) load_regs(kt + 1);

        const __half2* as = &As2[buf][0];
        const __half2* bs = &Bs2[buf][0];
        uint32_t af[4][4], bf[4][2];
        #pragma unroll
        for (int mf = 0; mf < 4; mf++) {
            const int r = wm * 64 + mf * 16 + lr;
            af[mf][0] = h2u(as[(r    ) * APAD2 + lc    ]);
            af[mf][1] = h2u(as[(r + 8) * APAD2 + lc    ]);
            af[mf][2] = h2u(as[(r    ) * APAD2 + lc + 4]);
            af[mf][3] = h2u(as[(r + 8) * APAD2 + lc + 4]);
        }
        #pragma unroll
        for (int nf = 0; nf < 4; nf++) {
            const int c = wn * 32 + nf * 8 + lr;
            bf[nf][0] = h2u(bs[(lc    ) * BPAD2 + c]);
            bf[nf][1] = h2u(bs[(lc + 4) * BPAD2 + c]);
        }
        #pragma unroll
        for (int mf = 0; mf < 4; mf++)
            #pragma unroll
            for (int nf = 0; nf < 4; nf++)
                mma_f16(acc[mf][nf][0], acc[mf][nf][1], acc[mf][nf][2], acc[mf][nf][3],
                        af[mf][0], af[mf][1], af[mf][2], af[mf][3],
                        bf[nf][0], bf[nf][1]);

        if (more) store_regs(buf ^ 1);
        __syncthreads();
    }

    // epilogue: acc[mf][nf][{c0,c1 row lr | c2,c3 row lr+8}], cols 2lc,2lc+1
    const int rb = m0 + wm * 64 + lr;
    const int cb = n0 + wn * 32 + 2 * lc;
    #pragma unroll
    for (int mf = 0; mf < 4; mf++) {
        #pragma unroll
        for (int nf = 0; nf < 4; nf++) {
            const int n = cb + nf * 8;
            #pragma unroll
            for (int half = 0; half < 2; half++) {
                const int m = rb + mf * 16 + half * 8;
                float2 v = make_float2(acc[mf][nf][half * 2], acc[mf][nf][half * 2 + 1]);
                if (mode == 1) {
                    *(float2*)(out + (size_t)m * DM + n) = v;
                } else {
                    const int b_ = m >> 11, s_ = m & (SEQ - 1);
                    const int h = n >> 6, d = n & 63;
                    *(float2*)(dstz + (((size_t)(b_ * NH + h)) * SEQ + s_) * DK + d) = v;
                }
            }
        }
    }
}

// ---------------- RoPE (unchanged) ------------------------------------------
__global__ void rope_kernel(const int* __restrict__ pos)
{
    const int NP = BATCH * NH * SEQ * (DK / 2);
    int idx = blockIdx.x * blockDim.x + threadIdx.x;
    if (idx >= NP) return;

    const int i  = idx & 31;
    const int s_ = (idx >> 5) & (SEQ - 1);
    const int bh = idx >> 16;
    const int b_ = bh >> 4;

    const int p = pos[b_ * SEQ + s_];
    const float e = (float)(2 * i) / 64.0f;
    const float invf = 1.0f / powf(10000.0f, e);
    const float ang = (float)p * invf;
    float sn, cs;
    sincosf(ang, &sn, &cs);

    const size_t base = (size_t)idx * 2;
    float qe = g_Q[base], qo = g_Q[base + 1];
    g_Q[base]     = qe * cs - qo * sn;
    g_Q[base + 1] = qe * sn + qo * cs;
    float ke = g_K[base], ko = g_K[base + 1];
    g_K[base]     = ke * cs - ko * sn;
    g_K[base + 1] = ke * sn + ko * cs;
}

// ---------------- fp16 MMA flash attention ----------------------------------
// CTA = 64 query rows, 4 warps x 16 rows. KV tile = 64. Causal.
// K stored as Ks[d/2][j] (k-interleaved for QK^T B-frags);
// V stored as Vs[j/2][d] (k-interleaved for PV B-frags).
// P feeds PV directly from registers (S accum layout == A-frag layout).
#define FBM 64
#define FBN 64
#define QP2 36   // banks 4*lr+lc distinct
#define KP2 72   // banks 8*lc+lr distinct
#define VP2 72

__global__ __launch_bounds__(128) void flash_f16_kernel()
{
    __shared__ __half2 Qs[FBM * QP2];        // [row][d/2]
    __shared__ __half2 Ks[(DK / 2) * KP2];   // [d/2][j]
    __shared__ __half2 Vs[(FBN / 2) * VP2];  // [j/2][d]

    const int bh = blockIdx.y;
    const int m0 = ((int)gridDim.x - 1 - (int)blockIdx.x) * FBM;  // heavy first
    const int tid  = threadIdx.x;
    const int lane = tid & 31;
    const int w    = tid >> 5;
    const int lr   = lane >> 2;
    const int lc   = lane & 3;

    const float* __restrict__ Qb = g_Q + (size_t)bh * SEQ * DK;
    const float* __restrict__ Kb = g_K + (size_t)bh * SEQ * DK;
    const float* __restrict__ Vb = g_V + (size_t)bh * SEQ * DK;

    // ---- stage Q (x 1/sqrt(64)) to half2 smem ----
    #pragma unroll
    for (int it = 0; it < 8; it++) {
        const int idx = tid + it * 128;       // 0..1023
        const int row = idx >> 4, dq = idx & 15;
        float4 v = *(const float4*)(Qb + (size_t)(m0 + row) * DK + dq * 4);
        Qs[row * QP2 + dq * 2    ] = __floats2half2_rn(v.x * 0.125f, v.y * 0.125f);
        Qs[row * QP2 + dq * 2 + 1] = __floats2half2_rn(v.z * 0.125f, v.w * 0.125f);
    }
    __syncthreads();

    uint32_t qf[4][4];
    #pragma unroll
    for (int ks = 0; ks < 4; ks++) {
        const int r = w * 16 + lr;
        qf[ks][0] = h2u(Qs[(r    ) * QP2 + ks * 8 + lc    ]);
        qf[ks][1] = h2u(Qs[(r + 8) * QP2 + ks * 8 + lc    ]);
        qf[ks][2] = h2u(Qs[(r    ) * QP2 + ks * 8 + lc + 4]);
        qf[ks][3] = h2u(Qs[(r + 8) * QP2 + ks * 8 + lc + 4]);
    }

    float o[8][4];
    #pragma unroll
    for (int n = 0; n < 8; n++)
        #pragma unroll
        for (int c = 0; c < 4; c++) o[n][c] = 0.f;
    float mrow0 = -1e30f, mrow1 = -1e30f, lrow0 = 0.f, lrow1 = 0.f;

    const int nt = m0 / FBN + 1;
    for (int t = 0; t < nt; t++) {
        const int j0 = t * FBN;
        __syncthreads();

        // K: Ks[dp][j] = half2(K[j][2dp], K[j][2dp+1])
        #pragma unroll
        for (int it = 0; it < 4; it++) {
            const int idx = tid + it * 128;      // 0..511
            const int jg = idx >> 5, dp = idx & 31;
            #pragma unroll
            for (int i = 0; i < 4; i++) {
                float2 f = *(const float2*)(Kb + (size_t)(j0 + jg * 4 + i) * DK + 2 * dp);
                Ks[dp * KP2 + jg * 4 + i] = __floats2half2_rn(f.x, f.y);
            }
        }
        // V: Vs[jp][d] = half2(V[2jp][d], V[2jp+1][d])
        #pragma unroll
        for (int it = 0; it < 4; it++) {
            const int idx = tid + it * 128;      // 0..511
            const int jp = idx >> 4, dq = idx & 15;
            float4 v0 = *(const float4*)(Vb + (size_t)(j0 + 2 * jp    ) * DK + dq * 4);
            float4 v1 = *(const float4*)(Vb + (size_t)(j0 + 2 * jp + 1) * DK + dq * 4);
            Vs[jp * VP2 + dq * 4 + 0] = __floats2half2_rn(v0.x, v1.x);
            Vs[jp * VP2 + dq * 4 + 1] = __floats2half2_rn(v0.y, v1.y);
            Vs[jp * VP2 + dq * 4 + 2] = __floats2half2_rn(v0.z, v1.z);
            Vs[jp * VP2 + dq * 4 + 3] = __floats2half2_rn(v0.w, v1.w);
        }
        __syncthreads();

        // ---- S = Q K^T ----
        float s[8][4];
        #pragma unroll
        for (int n = 0; n < 8; n++)
            #pragma unroll
            for (int c = 0; c < 4; c++) s[n][c] = 0.f;

        #pragma unroll
        for (int ks = 0; ks < 4; ks++) {
            #pragma unroll
            for (int n = 0; n < 8; n++) {
                const int c = n * 8 + lr;
                const uint32_t b0 = h2u(Ks[(ks * 8 + lc    ) * KP2 + c]);
                const uint32_t b1 = h2u(Ks[(ks * 8 + lc + 4) * KP2 + c]);
                mma_f16(s[n][0], s[n][1], s[n][2], s[n][3],
                        qf[ks][0], qf[ks][1], qf[ks][2], qf[ks][3], b0, b1);
            }
        }

        // ---- causal mask: diagonal tile only ----
        if (t == nt - 1) {
            const int r0 = w * 16 + lr;
            #pragma unroll
            for (int n = 0; n < 8; n++) {
                const int c0 = n * 8 + 2 * lc;
                if (c0     > r0)     s[n][0] = -1e30f;
                if (c0 + 1 > r0)     s[n][1] = -1e30f;
                if (c0     > r0 + 8) s[n][2] = -1e30f;
                if (c0 + 1 > r0 + 8) s[n][3] = -1e30f;
            }
        }

        // ---- online softmax ----
        float mx0 = -1e30f, mx1 = -1e30f;
        #pragma unroll
        for (int n = 0; n < 8; n++) {
            mx0 = fmaxf(mx0, fmaxf(s[n][0], s[n][1]));
            mx1 = fmaxf(mx1, fmaxf(s[n][2], s[n][3]));
        }
        mx0 = fmaxf(mx0, __shfl_xor_sync(0xffffffffu, mx0, 1));
        mx0 = fmaxf(mx0, __shfl_xor_sync(0xffffffffu, mx0, 2));
        mx1 = fmaxf(mx1, __shfl_xor_sync(0xffffffffu, mx1, 1));
        mx1 = fmaxf(mx1, __shfl_xor_sync(0xffffffffu, mx1, 2));

        const float mn0 = fmaxf(mrow0, mx0);
        const float mn1 = fmaxf(mrow1, mx1);
        const float sc0 = __expf(mrow0 - mn0);
        const float sc1 = __expf(mrow1 - mn1);
        lrow0 *= sc0; lrow1 *= sc1;
        #pragma unroll
        for (int n = 0; n < 8; n++) {
            o[n][0] *= sc0; o[n][1] *= sc0;
            o[n][2] *= sc1; o[n][3] *= sc1;
        }
        mrow0 = mn0; mrow1 = mn1;

        // P in registers, packed directly as PV A-fragments
        uint32_t pv[8][2];
        #pragma unroll
        for (int n = 0; n < 8; n++) {
            const float p0 = __expf(s[n][0] - mn0);
            const float p1 = __expf(s[n][1] - mn0);
            const float p2 = __expf(s[n][2] - mn1);
            const float p3 = __expf(s[n][3] - mn1);
            lrow0 += p0 + p1;
            lrow1 += p2 + p3;
            pv[n][0] = f2h2(p0, p1);   // row lr,   cols 2lc,2lc+1
            pv[n][1] = f2h2(p2, p3);   // row lr+8, cols 2lc,2lc+1
        }

        // ---- O += P V  (A-frags from pv registers) ----
        #pragma unroll
        for (int ks = 0; ks < 4; ks++) {
            const uint32_t a0 = pv[2 * ks    ][0];
            const uint32_t a1 = pv[2 * ks    ][1];
            const uint32_t a2 = pv[2 * ks + 1][0];
            const uint32_t a3 = pv[2 * ks + 1][1];
            #pragma unroll
            for (int n = 0; n < 8; n++) {
                const int c = n * 8 + lr;
                const uint32_t b0 = h2u(Vs[(ks * 8 + lc    ) * VP2 + c]);
                const uint32_t b1 = h2u(Vs[(ks * 8 + lc + 4) * VP2 + c]);
                mma_f16(o[n][0], o[n][1], o[n][2], o[n][3], a0, a1, a2, a3, b0, b1);
            }
        }
    }

    // ---- finalize ----
    lrow0 += __shfl_xor_sync(0xffffffffu, lrow0, 1);
    lrow0 += __shfl_xor_sync(0xffffffffu, lrow0, 2);
    lrow1 += __shfl_xor_sync(0xffffffffu, lrow1, 1);
    lrow1 += __shfl_xor_sync(0xffffffffu, lrow1, 2);
    const float inv0 = 1.0f / lrow0;
    const float inv1 = 1.0f / lrow1;

    const int b_ = bh >> 4, h = bh & 15;
    const int r0 = m0 + w * 16 + lr;
    const int r1 = r0 + 8;
    #pragma unroll
    for (int n = 0; n < 8; n++) {
        const int d = h * 64 + n * 8 + 2 * lc;
        *(float2*)(g_O + ((size_t)b_ * SEQ + r0) * DM + d) =
            make_float2(o[n][0] * inv0, o[n][1] * inv0);
        *(float2*)(g_O + ((size_t)b_ * SEQ + r1) * DM + d) =
            make_float2(o[n][2] * inv1, o[n][3] * inv1);
    }
}

// ---------------- launch ----------------------------------------------------
extern "C" void kernel_launch(void* const* d_in, const int* in_sizes, int n_in,
                              void* d_out, int out_size)
{
    (void)in_sizes; (void)n_in; (void)out_size;
    const float* x   = (const float*)d_in[0];
    const int*   pos = (const int*)  d_in[1];
    const float* WQ  = (const float*)d_in[2];
    const float* WK  = (const float*)d_in[3];
    const float* WV  = (const float*)d_in[4];
    const float* WO  = (const float*)d_in[5];
    float* out = (float*)d_out;

    dim3 gq(DM / TBN, (BATCH * SEQ) / TBM, 3);      // (8, 32, 3)
    gemm_f16_kernel<<<gq, 256>>>(x, WQ, WK, WV, nullptr, 0);

    const int NP = BATCH * NH * SEQ * (DK / 2);
    rope_kernel<<<(NP + 255) / 256, 256>>>(pos);

    dim3 gf(SEQ / FBM, BATCH * NH);                 // (32, 32)
    flash_f16_kernel<<<gf, 128>>>();

    dim3 go(DM / TBN, (BATCH * SEQ) / TBM, 1);      // (8, 32)
    gemm_f16_kernel<<<go, 256>>>(nullptr, WO, nullptr, nullptr, out, 1);
}

// round 8
// speedup vs baseline: 1.7267x; 1.0251x over previous
#include <cuda_runtime.h>
#include <cuda_fp16.h>
#include <math.h>
#include <stdint.h>

#define BATCH 2
#define SEQ   2048
#define DM    1024
#define NH    16
#define DK    64

// fp16 scratch (device globals; no allocation allowed)
__device__ __half g_Qh[BATCH * NH * SEQ * DK];   // [b,h,s,d] roped, x0.125
__device__ __half g_Kh[BATCH * NH * SEQ * DK];   // [b,h,s,d] roped
__device__ __half g_Vh[BATCH * NH * SEQ * DK];   // [b,h,s,d]
__device__ __half g_Oh[BATCH * SEQ * DM];        // [b,s,h*d]

__device__ __forceinline__ uint32_t h2u(__half2 h) {
    return *reinterpret_cast<uint32_t*>(&h);
}
__device__ __forceinline__ uint32_t f2h2u(float a, float b) {
    __half2 h = __floats2half2_rn(a, b);
    return *reinterpret_cast<uint32_t*>(&h);
}

// fp16 MMA, fp32 accumulate: D(16x8) += A(16x16) * B(16x8)
__device__ __forceinline__ void mma_f16(
    float& d0, float& d1, float& d2, float& d3,
    uint32_t a0, uint32_t a1, uint32_t a2, uint32_t a3,
    uint32_t b0, uint32_t b1)
{
    asm volatile(
        "mma.sync.aligned.m16n8k16.row.col.f32.f16.f16.f32 "
        "{%0,%1,%2,%3}, {%4,%5,%6,%7}, {%8,%9}, {%0,%1,%2,%3};\n"
        : "+f"(d0), "+f"(d1), "+f"(d2), "+f"(d3)
        : "r"(a0), "r"(a1), "r"(a2), "r"(a3), "r"(b0), "r"(b1));
}

#define TBM 128
#define TBN 128
#define TBK 16
#define APAD2 12
#define BPAD2 136

// ============ QKV GEMM: fp32 x,W -> fp16 Q/K/V with fused RoPE ==============
__global__ __launch_bounds__(256) void gemm_qkv_kernel(
    const float* __restrict__ A,
    const float* __restrict__ W0,
    const float* __restrict__ W1,
    const float* __restrict__ W2,
    const int* __restrict__ pos)
{
    __shared__ __half2 As2[2][TBM * APAD2];
    __shared__ __half2 Bs2[2][(TBK / 2) * BPAD2];

    const int z = blockIdx.z;
    const float* __restrict__ W = (z == 0) ? W0 : (z == 1) ? W1 : W2;
    __half* __restrict__ dsth = (z == 0) ? g_Qh : (z == 1) ? g_Kh : g_Vh;

    const int m0 = blockIdx.y * TBM;
    const int n0 = blockIdx.x * TBN;
    const int tid  = threadIdx.x;
    const int lane = tid & 31;
    const int wid  = tid >> 5;
    const int wm = wid >> 2;
    const int wn = wid & 3;
    const int lr = lane >> 2;
    const int lc = lane & 3;

    const int arow = tid >> 2;
    const int aq   = tid & 3;
    const int bkp  = tid >> 5;
    const int bnq  = tid & 31;

    float acc[4][4][4];
    #pragma unroll
    for (int i = 0; i < 4; i++)
        #pragma unroll
        for (int j = 0; j < 4; j++)
            #pragma unroll
            for (int r = 0; r < 4; r++) acc[i][j][r] = 0.f;

    float4 la[2], lb[2];
    auto load_regs = [&](int kt) {
        const int k0 = kt * TBK;
        #pragma unroll
        for (int i = 0; i < 2; i++)
            la[i] = *(const float4*)(A + (size_t)(m0 + arow + i * 64) * DM + k0 + aq * 4);
        lb[0] = *(const float4*)(W + (size_t)(k0 + 2 * bkp    ) * DM + n0 + bnq * 4);
        lb[1] = *(const float4*)(W + (size_t)(k0 + 2 * bkp + 1) * DM + n0 + bnq * 4);
    };
    auto store_regs = [&](int buf) {
        #pragma unroll
        for (int i = 0; i < 2; i++) {
            As2[buf][(arow + i * 64) * APAD2 + aq * 2    ] = __floats2half2_rn(la[i].x, la[i].y);
            As2[buf][(arow + i * 64) * APAD2 + aq * 2 + 1] = __floats2half2_rn(la[i].z, la[i].w);
        }
        const float* f0 = (const float*)&lb[0];
        const float* f1 = (const float*)&lb[1];
        #pragma unroll
        for (int i = 0; i < 4; i++)
            Bs2[buf][bkp * BPAD2 + bnq * 4 + i] = __floats2half2_rn(f0[i], f1[i]);
    };

    load_regs(0);
    store_regs(0);
    __syncthreads();

    const int NT = DM / TBK;
    for (int kt = 0; kt < NT; kt++) {
        const int buf = kt & 1;
        const bool more = (kt + 1 < NT);
        if (more) load_regs(kt + 1);

        const __half2* as = &As2[buf][0];
        const __half2* bs = &Bs2[buf][0];
        uint32_t af[4][4], bf[4][2];
        #pragma unroll
        for (int mf = 0; mf < 4; mf++) {
            const int r = wm * 64 + mf * 16 + lr;
            af[mf][0] = h2u(as[(r    ) * APAD2 + lc    ]);
            af[mf][1] = h2u(as[(r + 8) * APAD2 + lc    ]);
            af[mf][2] = h2u(as[(r    ) * APAD2 + lc + 4]);
            af[mf][3] = h2u(as[(r + 8) * APAD2 + lc + 4]);
        }
        #pragma unroll
        for (int nf = 0; nf < 4; nf++) {
            const int c = wn * 32 + nf * 8 + lr;
            bf[nf][0] = h2u(bs[(lc    ) * BPAD2 + c]);
            bf[nf][1] = h2u(bs[(lc + 4) * BPAD2 + c]);
        }
        #pragma unroll
        for (int mf = 0; mf < 4; mf++)
            #pragma unroll
            for (int nf = 0; nf < 4; nf++)
                mma_f16(acc[mf][nf][0], acc[mf][nf][1], acc[mf][nf][2], acc[mf][nf][3],
                        af[mf][0], af[mf][1], af[mf][2], af[mf][3],
                        bf[nf][0], bf[nf][1]);

        if (more) store_regs(buf ^ 1);
        __syncthreads();
    }

    // ---- epilogue with fused RoPE (z<2) + fp16 convert ----
    const int rb = m0 + wm * 64 + lr;
    const int cb = n0 + wn * 32 + 2 * lc;    // even column; pair (cb+nf*8, +1)

    float invf[4];
    #pragma unroll
    for (int nf = 0; nf < 4; nf++) {
        const int d = (cb + nf * 8) & 63;            // even
        invf[nf] = 1.0f / powf(10000.0f, (float)d / 64.0f);
    }
    const float qscale = (z == 0) ? 0.125f : 1.0f;

    #pragma unroll
    for (int mf = 0; mf < 4; mf++) {
        #pragma unroll
        for (int half = 0; half < 2; half++) {
            const int m = rb + mf * 16 + half * 8;
            const int b_ = m >> 11, s_ = m & (SEQ - 1);
            const float p = (float)pos[b_ * SEQ + s_];
            #pragma unroll
            for (int nf = 0; nf < 4; nf++) {
                const int n = cb + nf * 8;
                const int h = n >> 6, d = n & 63;
                const float ve = acc[mf][nf][half * 2];
                const float vo = acc[mf][nf][half * 2 + 1];
                float re, ro;
                if (z < 2) {
                    float sn, cs;
                    sincosf(p * invf[nf], &sn, &cs);
                    re = (ve * cs - vo * sn) * qscale;
                    ro = (ve * sn + vo * cs) * qscale;
                } else {
                    re = ve; ro = vo;
                }
                __half2* dp = (__half2*)(dsth + (((size_t)(b_ * NH + h)) * SEQ + s_) * DK + d);
                *dp = __floats2half2_rn(re, ro);
            }
        }
    }
}

// ============ WO GEMM: fp16 A (g_Oh) x fp32 W -> fp32 out ===================
__global__ __launch_bounds__(256) void gemm_out_kernel(
    const float* __restrict__ W,
    float* __restrict__ out)
{
    __shared__ __half2 As2[2][TBM * APAD2];
    __shared__ __half2 Bs2[2][(TBK / 2) * BPAD2];

    const __half* __restrict__ A = g_Oh;

    const int m0 = blockIdx.y * TBM;
    const int n0 = blockIdx.x * TBN;
    const int tid  = threadIdx.x;
    const int lane = tid & 31;
    const int wid  = tid >> 5;
    const int wm = wid >> 2;
    const int wn = wid & 3;
    const int lr = lane >> 2;
    const int lc = lane & 3;

    const int arow = tid >> 2;
    const int aq   = tid & 3;
    const int bkp  = tid >> 5;
    const int bnq  = tid & 31;

    float acc[4][4][4];
    #pragma unroll
    for (int i = 0; i < 4; i++)
        #pragma unroll
        for (int j = 0; j < 4; j++)
            #pragma unroll
            for (int r = 0; r < 4; r++) acc[i][j][r] = 0.f;

    uint2  la[2];
    float4 lb[2];
    auto load_regs = [&](int kt) {
        const int k0 = kt * TBK;
        #pragma unroll
        for (int i = 0; i < 2; i++)
            la[i] = *(const uint2*)(A + (size_t)(m0 + arow + i * 64) * DM + k0 + aq * 4);
        lb[0] = *(const float4*)(W + (size_t)(k0 + 2 * bkp    ) * DM + n0 + bnq * 4);
        lb[1] = *(const float4*)(W + (size_t)(k0 + 2 * bkp + 1) * DM + n0 + bnq * 4);
    };
    auto store_regs = [&](int buf) {
        #pragma unroll
        for (int i = 0; i < 2; i++)
            *(uint2*)&As2[buf][(arow + i * 64) * APAD2 + aq * 2] = la[i];
        const float* f0 = (const float*)&lb[0];
        const float* f1 = (const float*)&lb[1];
        #pragma unroll
        for (int i = 0; i < 4; i++)
            Bs2[buf][bkp * BPAD2 + bnq * 4 + i] = __floats2half2_rn(f0[i], f1[i]);
    };

    load_regs(0);
    store_regs(0);
    __syncthreads();

    const int NT = DM / TBK;
    for (int kt = 0; kt < NT; kt++) {
        const int buf = kt & 1;
        const bool more = (kt + 1 < NT);
        if (more) load_regs(kt + 1);

        const __half2* as = &As2[buf][0];
        const __half2* bs = &Bs2[buf][0];
        uint32_t af[4][4], bf[4][2];
        #pragma unroll
        for (int mf = 0; mf < 4; mf++) {
            const int r = wm * 64 + mf * 16 + lr;
            af[mf][0] = h2u(as[(r    ) * APAD2 + lc    ]);
            af[mf][1] = h2u(as[(r + 8) * APAD2 + lc    ]);
            af[mf][2] = h2u(as[(r    ) * APAD2 + lc + 4]);
            af[mf][3] = h2u(as[(r + 8) * APAD2 + lc + 4]);
        }
        #pragma unroll
        for (int nf = 0; nf < 4; nf++) {
            const int c = wn * 32 + nf * 8 + lr;
            bf[nf][0] = h2u(bs[(lc    ) * BPAD2 + c]);
            bf[nf][1] = h2u(bs[(lc + 4) * BPAD2 + c]);
        }
        #pragma unroll
        for (int mf = 0; mf < 4; mf++)
            #pragma unroll
            for (int nf = 0; nf < 4; nf++)
                mma_f16(acc[mf][nf][0], acc[mf][nf][1], acc[mf][nf][2], acc[mf][nf][3],
                        af[mf][0], af[mf][1], af[mf][2], af[mf][3],
                        bf[nf][0], bf[nf][1]);

        if (more) store_regs(buf ^ 1);
        __syncthreads();
    }

    const int rb = m0 + wm * 64 + lr;
    const int cb = n0 + wn * 32 + 2 * lc;
    #pragma unroll
    for (int mf = 0; mf < 4; mf++) {
        #pragma unroll
        for (int nf = 0; nf < 4; nf++) {
            const int n = cb + nf * 8;
            #pragma unroll
            for (int half = 0; half < 2; half++) {
                const int m = rb + mf * 16 + half * 8;
                *(float2*)(out + (size_t)m * DM + n) =
                    make_float2(acc[mf][nf][half * 2], acc[mf][nf][half * 2 + 1]);
            }
        }
    }
}

// ================= fp16 flash attention (all-fp16 I/O) ======================
#define FBM 64
#define FBN 64
#define QP2 36
#define KP2 72
#define VP2 72

__global__ __launch_bounds__(128) void flash_f16_kernel()
{
    __shared__ __half2 Qs[FBM * QP2];        // [row][d/2]
    __shared__ __half2 Ks[(DK / 2) * KP2];   // [d/2][j]
    __shared__ __half2 Vs[(FBN / 2) * VP2];  // [j/2][d]

    const int bh = blockIdx.y;
    const int m0 = ((int)gridDim.x - 1 - (int)blockIdx.x) * FBM;
    const int tid  = threadIdx.x;
    const int lane = tid & 31;
    const int w    = tid >> 5;
    const int lr   = lane >> 2;
    const int lc   = lane & 3;

    const __half* __restrict__ Qb = g_Qh + (size_t)bh * SEQ * DK;
    const __half2* __restrict__ Kb2 = (const __half2*)(g_Kh + (size_t)bh * SEQ * DK);
    const __half* __restrict__ Vb = g_Vh + (size_t)bh * SEQ * DK;

    // ---- stage Q (already roped+scaled fp16): 64 rows x 8 uint4 ----
    #pragma unroll
    for (int it = 0; it < 4; it++) {
        const int idx = tid + it * 128;       // 0..511
        const int row = idx >> 3, dq = idx & 7;
        *(uint4*)&Qs[row * QP2 + dq * 4] =
            *(const uint4*)(Qb + (size_t)(m0 + row) * DK + dq * 8);
    }
    __syncthreads();

    uint32_t qf[4][4];
    #pragma unroll
    for (int ks = 0; ks < 4; ks++) {
        const int r = w * 16 + lr;
        qf[ks][0] = h2u(Qs[(r    ) * QP2 + ks * 8 + lc    ]);
        qf[ks][1] = h2u(Qs[(r + 8) * QP2 + ks * 8 + lc    ]);
        qf[ks][2] = h2u(Qs[(r    ) * QP2 + ks * 8 + lc + 4]);
        qf[ks][3] = h2u(Qs[(r + 8) * QP2 + ks * 8 + lc + 4]);
    }

    float o[8][4];
    #pragma unroll
    for (int n = 0; n < 8; n++)
        #pragma unroll
        for (int c = 0; c < 4; c++) o[n][c] = 0.f;
    float mrow0 = -1e30f, mrow1 = -1e30f, lrow0 = 0.f, lrow1 = 0.f;

    const int nt = m0 / FBN + 1;
    for (int t = 0; t < nt; t++) {
        const int j0 = t * FBN;
        __syncthreads();

        // K: Ks[dp][j] = Kb2[j][dp]  (transpose gather, 4B coalesced rows)
        #pragma unroll
        for (int it = 0; it < 4; it++) {
            const int idx = tid + it * 128;      // 0..511
            const int jg = idx >> 5, dp = idx & 31;
            #pragma unroll
            for (int i = 0; i < 4; i++)
                Ks[dp * KP2 + jg * 4 + i] = Kb2[(size_t)(j0 + jg * 4 + i) * 32 + dp];
        }
        // V: Vs[jp][d] = half2(V[2jp][d], V[2jp+1][d])  (row-pair interleave)
        #pragma unroll
        for (int it = 0; it < 4; it++) {
            const int idx = tid + it * 128;      // 0..511
            const int jp = idx >> 4, dq2 = idx & 15;   // d block of 4
            uint2 u0 = *(const uint2*)(Vb + (size_t)(j0 + 2 * jp    ) * DK + dq2 * 4);
            uint2 u1 = *(const uint2*)(Vb + (size_t)(j0 + 2 * jp + 1) * DK + dq2 * 4);
            __half2 a0 = *(__half2*)&u0.x, a1 = *(__half2*)&u0.y;
            __half2 c0 = *(__half2*)&u1.x, c1 = *(__half2*)&u1.y;
            Vs[jp * VP2 + dq2 * 4 + 0] = __lows2half2 (a0, c0);
            Vs[jp * VP2 + dq2 * 4 + 1] = __highs2half2(a0, c0);
            Vs[jp * VP2 + dq2 * 4 + 2] = __lows2half2 (a1, c1);
            Vs[jp * VP2 + dq2 * 4 + 3] = __highs2half2(a1, c1);
        }
        __syncthreads();

        // ---- S = Q K^T ----
        float s[8][4];
        #pragma unroll
        for (int n = 0; n < 8; n++)
            #pragma unroll
            for (int c = 0; c < 4; c++) s[n][c] = 0.f;

        #pragma unroll
        for (int ks = 0; ks < 4; ks++) {
            #pragma unroll
            for (int n = 0; n < 8; n++) {
                const int c = n * 8 + lr;
                const uint32_t b0 = h2u(Ks[(ks * 8 + lc    ) * KP2 + c]);
                const uint32_t b1 = h2u(Ks[(ks * 8 + lc + 4) * KP2 + c]);
                mma_f16(s[n][0], s[n][1], s[n][2], s[n][3],
                        qf[ks][0], qf[ks][1], qf[ks][2], qf[ks][3], b0, b1);
            }
        }

        if (t == nt - 1) {           // diagonal tile mask
            const int r0 = w * 16 + lr;
            #pragma unroll
            for (int n = 0; n < 8; n++) {
                const int c0 = n * 8 + 2 * lc;
                if (c0     > r0)     s[n][0] = -1e30f;
                if (c0 + 1 > r0)     s[n][1] = -1e30f;
                if (c0     > r0 + 8) s[n][2] = -1e30f;
                if (c0 + 1 > r0 + 8) s[n][3] = -1e30f;
            }
        }

        float mx0 = -1e30f, mx1 = -1e30f;
        #pragma unroll
        for (int n = 0; n < 8; n++) {
            mx0 = fmaxf(mx0, fmaxf(s[n][0], s[n][1]));
            mx1 = fmaxf(mx1, fmaxf(s[n][2], s[n][3]));
        }
        mx0 = fmaxf(mx0, __shfl_xor_sync(0xffffffffu, mx0, 1));
        mx0 = fmaxf(mx0, __shfl_xor_sync(0xffffffffu, mx0, 2));
        mx1 = fmaxf(mx1, __shfl_xor_sync(0xffffffffu, mx1, 1));
        mx1 = fmaxf(mx1, __shfl_xor_sync(0xffffffffu, mx1, 2));

        const float mn0 = fmaxf(mrow0, mx0);
        const float mn1 = fmaxf(mrow1, mx1);
        const float sc0 = __expf(mrow0 - mn0);
        const float sc1 = __expf(mrow1 - mn1);
        lrow0 *= sc0; lrow1 *= sc1;
        #pragma unroll
        for (int n = 0; n < 8; n++) {
            o[n][0] *= sc0; o[n][1] *= sc0;
            o[n][2] *= sc1; o[n][3] *= sc1;
        }
        mrow0 = mn0; mrow1 = mn1;

        uint32_t pv[8][2];
        #pragma unroll
        for (int n = 0; n < 8; n++) {
            const float p0 = __expf(s[n][0] - mn0);
            const float p1 = __expf(s[n][1] - mn0);
            const float p2 = __expf(s[n][2] - mn1);
            const float p3 = __expf(s[n][3] - mn1);
            lrow0 += p0 + p1;
            lrow1 += p2 + p3;
            pv[n][0] = f2h2u(p0, p1);
            pv[n][1] = f2h2u(p2, p3);
        }

        #pragma unroll
        for (int ks = 0; ks < 4; ks++) {
            const uint32_t a0 = pv[2 * ks    ][0];
            const uint32_t a1 = pv[2 * ks    ][1];
            const uint32_t a2 = pv[2 * ks + 1][0];
            const uint32_t a3 = pv[2 * ks + 1][1];
            #pragma unroll
            for (int n = 0; n < 8; n++) {
                const int c = n * 8 + lr;
                const uint32_t b0 = h2u(Vs[(ks * 8 + lc    ) * VP2 + c]);
                const uint32_t b1 = h2u(Vs[(ks * 8 + lc + 4) * VP2 + c]);
                mma_f16(o[n][0], o[n][1], o[n][2], o[n][3], a0, a1, a2, a3, b0, b1);
            }
        }
    }

    lrow0 += __shfl_xor_sync(0xffffffffu, lrow0, 1);
    lrow0 += __shfl_xor_sync(0xffffffffu, lrow0, 2);
    lrow1 += __shfl_xor_sync(0xffffffffu, lrow1, 1);
    lrow1 += __shfl_xor_sync(0xffffffffu, lrow1, 2);
    const float inv0 = 1.0f / lrow0;
    const float inv1 = 1.0f / lrow1;

    const int b_ = bh >> 4, h = bh & 15;
    const int r0 = m0 + w * 16 + lr;
    const int r1 = r0 + 8;
    #pragma unroll
    for (int n = 0; n < 8; n++) {
        const int d = h * 64 + n * 8 + 2 * lc;
        *(__half2*)(g_Oh + ((size_t)b_ * SEQ + r0) * DM + d) =
            __floats2half2_rn(o[n][0] * inv0, o[n][1] * inv0);
        *(__half2*)(g_Oh + ((size_t)b_ * SEQ + r1) * DM + d) =
            __floats2half2_rn(o[n][2] * inv1, o[n][3] * inv1);
    }
}

// ---------------- launch ----------------------------------------------------
extern "C" void kernel_launch(void* const* d_in, const int* in_sizes, int n_in,
                              void* d_out, int out_size)
{
    (void)in_sizes; (void)n_in; (void)out_size;
    const float* x   = (const float*)d_in[0];
    const int*   pos = (const int*)  d_in[1];
    const float* WQ  = (const float*)d_in[2];
    const float* WK  = (const float*)d_in[3];
    const float* WV  = (const float*)d_in[4];
    const float* WO  = (const float*)d_in[5];
    float* out = (float*)d_out;

    dim3 gq(DM / TBN, (BATCH * SEQ) / TBM, 3);      // (8, 32, 3)
    gemm_qkv_kernel<<<gq, 256>>>(x, WQ, WK, WV, pos);

    dim3 gf(SEQ / FBM, BATCH * NH);                 // (32, 32)
    flash_f16_kernel<<<gf, 128>>>();

    dim3 go(DM / TBN, (BATCH * SEQ) / TBM, 1);      // (8, 32)
    gemm_out_kernel<<<go, 256>>>(WO, out);
}

// round 9
// speedup vs baseline: 1.8745x; 1.0856x over previous
#include <cuda_runtime.h>
#include <cuda_fp16.h>
#include <math.h>
#include <stdint.h>

#define BATCH 2
#define SEQ   2048
#define DM    1024
#define NH    16
#define DK    64

// fp16 scratch (device globals; no allocation allowed)
__device__ __half g_xh[BATCH * SEQ * DM];        // x in fp16
__device__ __half g_Wqh[DM * DM];
__device__ __half g_Wkh[DM * DM];
__device__ __half g_Wvh[DM * DM];
__device__ __half g_Woh[DM * DM];
__device__ __half g_Qh[BATCH * NH * SEQ * DK];   // [b,h,s,d] roped, x0.125
__device__ __half g_Kh[BATCH * NH * SEQ * DK];   // [b,h,s,d] roped
__device__ __half g_Vh[BATCH * NH * SEQ * DK];   // [b,h,s,d]
__device__ __half g_Oh[BATCH * SEQ * DM];        // [b,s,h*d]

__device__ __forceinline__ uint32_t h2u(__half2 h) {
    return *reinterpret_cast<uint32_t*>(&h);
}
__device__ __forceinline__ uint32_t f2h2u(float a, float b) {
    __half2 h = __floats2half2_rn(a, b);
    return *reinterpret_cast<uint32_t*>(&h);
}

__device__ __forceinline__ void mma_f16(
    float& d0, float& d1, float& d2, float& d3,
    uint32_t a0, uint32_t a1, uint32_t a2, uint32_t a3,
    uint32_t b0, uint32_t b1)
{
    asm volatile(
        "mma.sync.aligned.m16n8k16.row.col.f32.f16.f16.f32 "
        "{%0,%1,%2,%3}, {%4,%5,%6,%7}, {%8,%9}, {%0,%1,%2,%3};\n"
        : "+f"(d0), "+f"(d1), "+f"(d2), "+f"(d3)
        : "r"(a0), "r"(a1), "r"(a2), "r"(a3), "r"(b0), "r"(b1));
}

// ================= fp32 -> fp16 pre-convert (x, WQ, WK, WV, WO) =============
#define NX (BATCH * SEQ * DM)    // 4194304
#define NW (DM * DM)             // 1048576

__global__ __launch_bounds__(256) void cvt_kernel(
    const float* __restrict__ x,
    const float* __restrict__ wq,
    const float* __restrict__ wk,
    const float* __restrict__ wv,
    const float* __restrict__ wo)
{
    const size_t base = ((size_t)blockIdx.x * 256 + threadIdx.x) * 8;
    const float* src;
    __half* dst;
    size_t off;
    if (base < NX)               { src = x;  dst = g_xh;  off = base; }
    else if (base < NX + NW)     { src = wq; dst = g_Wqh; off = base - NX; }
    else if (base < NX + 2 * NW) { src = wk; dst = g_Wkh; off = base - NX - NW; }
    else if (base < NX + 3 * NW) { src = wv; dst = g_Wvh; off = base - NX - 2 * NW; }
    else                         { src = wo; dst = g_Woh; off = base - NX - 3 * NW; }

    float4 f0 = *(const float4*)(src + off);
    float4 f1 = *(const float4*)(src + off + 4);
    uint4 o;
    o.x = f2h2u(f0.x, f0.y); o.y = f2h2u(f0.z, f0.w);
    o.z = f2h2u(f1.x, f1.y); o.w = f2h2u(f1.z, f1.w);
    *(uint4*)(dst + off) = o;
}

// ================= fp16 GEMM core: 128x128x32 tiles, 8 warps ================
#define TBM 128
#define TBN 128
#define TBK 32
#define APAD2 20    // As2 row stride in half2 (16 data + 4 pad)
#define BPAD2 136   // Bs2 row stride in half2

// Shared-loop GEMM body; epilogue differs per kernel.
// A [M,K] fp16 row-major, W [K,N] fp16 row-major.
#define GEMM_BODY(A_, W_)                                                      \
    __shared__ __half2 As2[2][TBM * APAD2];                                    \
    __shared__ __half2 Bs2[2][(TBK / 2) * BPAD2];                              \
    const int m0 = blockIdx.y * TBM;                                           \
    const int n0 = blockIdx.x * TBN;                                           \
    const int tid  = threadIdx.x;                                              \
    const int lane = tid & 31;                                                 \
    const int wid  = tid >> 5;                                                 \
    const int wm = wid >> 2;                                                   \
    const int wn = wid & 3;                                                    \
    const int lr = lane >> 2;                                                  \
    const int lc = lane & 3;                                                   \
    const int arow = tid >> 1;          /* 0..127 */                           \
    const int aq   = tid & 1;           /* half-row: cols aq*16.. (halves) */  \
    const int bkp  = tid >> 4;          /* 0..15: k-pair row */                \
    const int bnq  = tid & 15;          /* col chunk of 8 halves */            \
    float acc[4][4][4];                                                        \
    _Pragma("unroll")                                                          \
    for (int i = 0; i < 4; i++)                                                \
        _Pragma("unroll")                                                      \
        for (int j = 0; j < 4; j++)                                            \
            _Pragma("unroll")                                                  \
            for (int r = 0; r < 4; r++) acc[i][j][r] = 0.f;                    \
    uint4 ua[2], ub[2];                                                        \
    auto load_regs = [&](int kt) {                                             \
        const int k0 = kt * TBK;                                               \
        _Pragma("unroll")                                                      \
        for (int i = 0; i < 2; i++)                                            \
            ua[i] = *(const uint4*)(A_ + (size_t)(m0 + arow) * DM + k0         \
                                    + aq * 16 + i * 8);                        \
        ub[0] = *(const uint4*)(W_ + (size_t)(k0 + 2 * bkp    ) * DM + n0 + bnq * 8); \
        ub[1] = *(const uint4*)(W_ + (size_t)(k0 + 2 * bkp + 1) * DM + n0 + bnq * 8); \
    };                                                                         \
    auto store_regs = [&](int buf) {                                           \
        _Pragma("unroll")                                                      \
        for (int i = 0; i < 2; i++)                                            \
            *(uint4*)&As2[buf][arow * APAD2 + aq * 8 + i * 4] = ua[i];         \
        const __half2* a2 = (const __half2*)&ub[0];                            \
        const __half2* b2 = (const __half2*)&ub[1];                            \
        __half2 h[8];                                                          \
        _Pragma("unroll")                                                      \
        for (int j = 0; j < 4; j++) {                                          \
            h[2 * j    ] = __lows2half2 (a2[j], b2[j]);                        \
            h[2 * j + 1] = __highs2half2(a2[j], b2[j]);                        \
        }                                                                      \
        *(uint4*)&Bs2[buf][bkp * BPAD2 + bnq * 8    ] = *(uint4*)&h[0];        \
        *(uint4*)&Bs2[buf][bkp * BPAD2 + bnq * 8 + 4] = *(uint4*)&h[4];        \
    };                                                                         \
    load_regs(0);                                                              \
    store_regs(0);                                                             \
    __syncthreads();                                                           \
    const int NT = DM / TBK;   /* 32 */                                        \
    for (int kt = 0; kt < NT; kt++) {                                          \
        const int buf = kt & 1;                                                \
        const bool more = (kt + 1 < NT);                                       \
        if (more) load_regs(kt + 1);                                           \
        const __half2* as = &As2[buf][0];                                      \
        const __half2* bs = &Bs2[buf][0];                                      \
        _Pragma("unroll")                                                      \
        for (int ks = 0; ks < 2; ks++) {                                       \
            uint32_t af[4][4], bf[4][2];                                       \
            _Pragma("unroll")                                                  \
            for (int mf = 0; mf < 4; mf++) {                                   \
                const int r = wm * 64 + mf * 16 + lr;                          \
                af[mf][0] = h2u(as[(r    ) * APAD2 + ks * 8 + lc    ]);        \
                af[mf][1] = h2u(as[(r + 8) * APAD2 + ks * 8 + lc    ]);        \
                af[mf][2] = h2u(as[(r    ) * APAD2 + ks * 8 + lc + 4]);        \
                af[mf][3] = h2u(as[(r + 8) * APAD2 + ks * 8 + lc + 4]);        \
            }                                                                  \
            _Pragma("unroll")                                                  \
            for (int nf = 0; nf < 4; nf++) {                                   \
                const int c = wn * 32 + nf * 8 + lr;                           \
                bf[nf][0] = h2u(bs[(ks * 8 + lc    ) * BPAD2 + c]);            \
                bf[nf][1] = h2u(bs[(ks * 8 + lc + 4) * BPAD2 + c]);            \
            }                                                                  \
            _Pragma("unroll")                                                  \
            for (int mf = 0; mf < 4; mf++)                                     \
                _Pragma("unroll")                                              \
                for (int nf = 0; nf < 4; nf++)                                 \
                    mma_f16(acc[mf][nf][0], acc[mf][nf][1],                    \
                            acc[mf][nf][2], acc[mf][nf][3],                    \
                            af[mf][0], af[mf][1], af[mf][2], af[mf][3],        \
                            bf[nf][0], bf[nf][1]);                             \
        }                                                                      \
        if (more) store_regs(buf ^ 1);                                         \
        __syncthreads();                                                       \
    }

// ============ QKV GEMM: fp16 x,W -> fp16 Q/K/V with fused RoPE ==============
__global__ __launch_bounds__(256) void gemm_qkv_kernel(const int* __restrict__ pos)
{
    const int z = blockIdx.z;
    const __half* __restrict__ W =
        (z == 0) ? g_Wqh : (z == 1) ? g_Wkh : g_Wvh;
    __half* __restrict__ dsth = (z == 0) ? g_Qh : (z == 1) ? g_Kh : g_Vh;
    const __half* __restrict__ A = g_xh;

    GEMM_BODY(A, W)

    // ---- epilogue with fused RoPE (z<2) + fp16 convert ----
    const int rb = m0 + wm * 64 + lr;
    const int cb = n0 + wn * 32 + 2 * lc;

    float invf[4];
    #pragma unroll
    for (int nf = 0; nf < 4; nf++) {
        const int d = (cb + nf * 8) & 63;
        invf[nf] = 1.0f / powf(10000.0f, (float)d / 64.0f);
    }
    const float qscale = (z == 0) ? 0.125f : 1.0f;

    #pragma unroll
    for (int mf = 0; mf < 4; mf++) {
        #pragma unroll
        for (int half = 0; half < 2; half++) {
            const int m = rb + mf * 16 + half * 8;
            const int b_ = m >> 11, s_ = m & (SEQ - 1);
            const float p = (float)pos[b_ * SEQ + s_];
            #pragma unroll
            for (int nf = 0; nf < 4; nf++) {
                const int n = cb + nf * 8;
                const int h = n >> 6, d = n & 63;
                const float ve = acc[mf][nf][half * 2];
                const float vo = acc[mf][nf][half * 2 + 1];
                float re, ro;
                if (z < 2) {
                    float sn, cs;
                    sincosf(p * invf[nf], &sn, &cs);
                    re = (ve * cs - vo * sn) * qscale;
                    ro = (ve * sn + vo * cs) * qscale;
                } else {
                    re = ve; ro = vo;
                }
                __half2* dp = (__half2*)(dsth + (((size_t)(b_ * NH + h)) * SEQ + s_) * DK + d);
                *dp = __floats2half2_rn(re, ro);
            }
        }
    }
}

// ============ WO GEMM: fp16 g_Oh x fp16 g_Woh -> fp32 out ===================
__global__ __launch_bounds__(256) void gemm_out_kernel(float* __restrict__ out)
{
    const __half* __restrict__ A = g_Oh;
    const __half* __restrict__ W = g_Woh;

    GEMM_BODY(A, W)

    const int rb = m0 + wm * 64 + lr;
    const int cb = n0 + wn * 32 + 2 * lc;
    #pragma unroll
    for (int mf = 0; mf < 4; mf++) {
        #pragma unroll
        for (int nf = 0; nf < 4; nf++) {
            const int n = cb + nf * 8;
            #pragma unroll
            for (int half = 0; half < 2; half++) {
                const int m = rb + mf * 16 + half * 8;
                *(float2*)(out + (size_t)m * DM + n) =
                    make_float2(acc[mf][nf][half * 2], acc[mf][nf][half * 2 + 1]);
            }
        }
    }
}

// ================= fp16 flash attention (unchanged from R8) =================
#define FBM 64
#define FBN 64
#define QP2 36
#define KP2 72
#define VP2 72

__global__ __launch_bounds__(128) void flash_f16_kernel()
{
    __shared__ __half2 Qs[FBM * QP2];
    __shared__ __half2 Ks[(DK / 2) * KP2];
    __shared__ __half2 Vs[(FBN / 2) * VP2];

    const int bh = blockIdx.y;
    const int m0 = ((int)gridDim.x - 1 - (int)blockIdx.x) * FBM;
    const int tid  = threadIdx.x;
    const int lane = tid & 31;
    const int w    = tid >> 5;
    const int lr   = lane >> 2;
    const int lc   = lane & 3;

    const __half* __restrict__ Qb = g_Qh + (size_t)bh * SEQ * DK;
    const __half2* __restrict__ Kb2 = (const __half2*)(g_Kh + (size_t)bh * SEQ * DK);
    const __half* __restrict__ Vb = g_Vh + (size_t)bh * SEQ * DK;

    #pragma unroll
    for (int it = 0; it < 4; it++) {
        const int idx = tid + it * 128;
        const int row = idx >> 3, dq = idx & 7;
        *(uint4*)&Qs[row * QP2 + dq * 4] =
            *(const uint4*)(Qb + (size_t)(m0 + row) * DK + dq * 8);
    }
    __syncthreads();

    uint32_t qf[4][4];
    #pragma unroll
    for (int ks = 0; ks < 4; ks++) {
        const int r = w * 16 + lr;
        qf[ks][0] = h2u(Qs[(r    ) * QP2 + ks * 8 + lc    ]);
        qf[ks][1] = h2u(Qs[(r + 8) * QP2 + ks * 8 + lc    ]);
        qf[ks][2] = h2u(Qs[(r    ) * QP2 + ks * 8 + lc + 4]);
        qf[ks][3] = h2u(Qs[(r + 8) * QP2 + ks * 8 + lc + 4]);
    }

    float o[8][4];
    #pragma unroll
    for (int n = 0; n < 8; n++)
        #pragma unroll
        for (int c = 0; c < 4; c++) o[n][c] = 0.f;
    float mrow0 = -1e30f, mrow1 = -1e30f, lrow0 = 0.f, lrow1 = 0.f;

    const int nt = m0 / FBN + 1;
    for (int t = 0; t < nt; t++) {
        const int j0 = t * FBN;
        __syncthreads();

        #pragma unroll
        for (int it = 0; it < 4; it++) {
            const int idx = tid + it * 128;
            const int jg = idx >> 5, dp = idx & 31;
            #pragma unroll
            for (int i = 0; i < 4; i++)
                Ks[dp * KP2 + jg * 4 + i] = Kb2[(size_t)(j0 + jg * 4 + i) * 32 + dp];
        }
        #pragma unroll
        for (int it = 0; it < 4; it++) {
            const int idx = tid + it * 128;
            const int jp = idx >> 4, dq2 = idx & 15;
            uint2 u0 = *(const uint2*)(Vb + (size_t)(j0 + 2 * jp    ) * DK + dq2 * 4);
            uint2 u1 = *(const uint2*)(Vb + (size_t)(j0 + 2 * jp + 1) * DK + dq2 * 4);
            __half2 a0 = *(__half2*)&u0.x, a1 = *(__half2*)&u0.y;
            __half2 c0 = *(__half2*)&u1.x, c1 = *(__half2*)&u1.y;
            Vs[jp * VP2 + dq2 * 4 + 0] = __lows2half2 (a0, c0);
            Vs[jp * VP2 + dq2 * 4 + 1] = __highs2half2(a0, c0);
            Vs[jp * VP2 + dq2 * 4 + 2] = __lows2half2 (a1, c1);
            Vs[jp * VP2 + dq2 * 4 + 3] = __highs2half2(a1, c1);
        }
        __syncthreads();

        float s[8][4];
        #pragma unroll
        for (int n = 0; n < 8; n++)
            #pragma unroll
            for (int c = 0; c < 4; c++) s[n][c] = 0.f;

        #pragma unroll
        for (int ks = 0; ks < 4; ks++) {
            #pragma unroll
            for (int n = 0; n < 8; n++) {
                const int c = n * 8 + lr;
                const uint32_t b0 = h2u(Ks[(ks * 8 + lc    ) * KP2 + c]);
                const uint32_t b1 = h2u(Ks[(ks * 8 + lc + 4) * KP2 + c]);
                mma_f16(s[n][0], s[n][1], s[n][2], s[n][3],
                        qf[ks][0], qf[ks][1], qf[ks][2], qf[ks][3], b0, b1);
            }
        }

        if (t == nt - 1) {
            const int r0 = w * 16 + lr;
            #pragma unroll
            for (int n = 0; n < 8; n++) {
                const int c0 = n * 8 + 2 * lc;
                if (c0     > r0)     s[n][0] = -1e30f;
                if (c0 + 1 > r0)     s[n][1] = -1e30f;
                if (c0     > r0 + 8) s[n][2] = -1e30f;
                if (c0 + 1 > r0 + 8) s[n][3] = -1e30f;
            }
        }

        float mx0 = -1e30f, mx1 = -1e30f;
        #pragma unroll
        for (int n = 0; n < 8; n++) {
            mx0 = fmaxf(mx0, fmaxf(s[n][0], s[n][1]));
            mx1 = fmaxf(mx1, fmaxf(s[n][2], s[n][3]));
        }
        mx0 = fmaxf(mx0, __shfl_xor_sync(0xffffffffu, mx0, 1));
        mx0 = fmaxf(mx0, __shfl_xor_sync(0xffffffffu, mx0, 2));
        mx1 = fmaxf(mx1, __shfl_xor_sync(0xffffffffu, mx1, 1));
        mx1 = fmaxf(mx1, __shfl_xor_sync(0xffffffffu, mx1, 2));

        const float mn0 = fmaxf(mrow0, mx0);
        const float mn1 = fmaxf(mrow1, mx1);
        const float sc0 = __expf(mrow0 - mn0);
        const float sc1 = __expf(mrow1 - mn1);
        lrow0 *= sc0; lrow1 *= sc1;
        #pragma unroll
        for (int n = 0; n < 8; n++) {
            o[n][0] *= sc0; o[n][1] *= sc0;
            o[n][2] *= sc1; o[n][3] *= sc1;
        }
        mrow0 = mn0; mrow1 = mn1;

        uint32_t pv[8][2];
        #pragma unroll
        for (int n = 0; n < 8; n++) {
            const float p0 = __expf(s[n][0] - mn0);
            const float p1 = __expf(s[n][1] - mn0);
            const float p2 = __expf(s[n][2] - mn1);
            const float p3 = __expf(s[n][3] - mn1);
            lrow0 += p0 + p1;
            lrow1 += p2 + p3;
            pv[n][0] = f2h2u(p0, p1);
            pv[n][1] = f2h2u(p2, p3);
        }

        #pragma unroll
        for (int ks = 0; ks < 4; ks++) {
            const uint32_t a0 = pv[2 * ks    ][0];
            const uint32_t a1 = pv[2 * ks    ][1];
            const uint32_t a2 = pv[2 * ks + 1][0];
            const uint32_t a3 = pv[2 * ks + 1][1];
            #pragma unroll
            for (int n = 0; n < 8; n++) {
                const int c = n * 8 + lr;
                const uint32_t b0 = h2u(Vs[(ks * 8 + lc    ) * VP2 + c]);
                const uint32_t b1 = h2u(Vs[(ks * 8 + lc + 4) * VP2 + c]);
                mma_f16(o[n][0], o[n][1], o[n][2], o[n][3], a0, a1, a2, a3, b0, b1);
            }
        }
    }

    lrow0 += __shfl_xor_sync(0xffffffffu, lrow0, 1);
    lrow0 += __shfl_xor_sync(0xffffffffu, lrow0, 2);
    lrow1 += __shfl_xor_sync(0xffffffffu, lrow1, 1);
    lrow1 += __shfl_xor_sync(0xffffffffu, lrow1, 2);
    const float inv0 = 1.0f / lrow0;
    const float inv1 = 1.0f / lrow1;

    const int b_ = bh >> 4, h = bh & 15;
    const int r0 = m0 + w * 16 + lr;
    const int r1 = r0 + 8;
    #pragma unroll
    for (int n = 0; n < 8; n++) {
        const int d = h * 64 + n * 8 + 2 * lc;
        *(__half2*)(g_Oh + ((size_t)b_ * SEQ + r0) * DM + d) =
            __floats2half2_rn(o[n][0] * inv0, o[n][1] * inv0);
        *(__half2*)(g_Oh + ((size_t)b_ * SEQ + r1) * DM + d) =
            __floats2half2_rn(o[n][2] * inv1, o[n][3] * inv1);
    }
}

// ---------------- launch ----------------------------------------------------
extern "C" void kernel_launch(void* const* d_in, const int* in_sizes, int n_in,
                              void* d_out, int out_size)
{
    (void)in_sizes; (void)n_in; (void)out_size;
    const float* x   = (const float*)d_in[0];
    const int*   pos = (const int*)  d_in[1];
    const float* WQ  = (const float*)d_in[2];
    const float* WK  = (const float*)d_in[3];
    const float* WV  = (const float*)d_in[4];
    const float* WO  = (const float*)d_in[5];
    float* out = (float*)d_out;

    const int ncvt = (NX + 4 * NW) / (8 * 256);     // 4096 blocks
    cvt_kernel<<<ncvt, 256>>>(x, WQ, WK, WV, WO);

    dim3 gq(DM / TBN, (BATCH * SEQ) / TBM, 3);      // (8, 32, 3)
    gemm_qkv_kernel<<<gq, 256>>>(pos);

    dim3 gf(SEQ / FBM, BATCH * NH);                 // (32, 32)
    flash_f16_kernel<<<gf, 128>>>();

    dim3 go(DM / TBN, (BATCH * SEQ) / TBM, 1);      // (8, 32)
    gemm_out_kernel<<<go, 256>>>(out);
}

// round 10
// speedup vs baseline: 2.0977x; 1.1191x over previous
#include <cuda_runtime.h>
#include <cuda_fp16.h>
#include <math.h>
#include <stdint.h>

#define BATCH 2
#define SEQ   2048
#define DM    1024
#define NH    16
#define DK    64

// fp16 scratch (device globals; no allocation allowed)
__device__ __half g_xh[BATCH * SEQ * DM];
__device__ __half g_Wqh[DM * DM];
__device__ __half g_Wkh[DM * DM];
__device__ __half g_Wvh[DM * DM];
__device__ __half g_Woh[DM * DM];
__device__ __half g_Qh[BATCH * NH * SEQ * DK];   // roped, x0.125
__device__ __half g_Kh[BATCH * NH * SEQ * DK];   // roped
__device__ __half g_Vh[BATCH * NH * SEQ * DK];
__device__ __half g_Oh[BATCH * SEQ * DM];

__device__ __forceinline__ uint32_t h2u(__half2 h) {
    return *reinterpret_cast<uint32_t*>(&h);
}
__device__ __forceinline__ uint32_t f2h2u(float a, float b) {
    __half2 h = __floats2half2_rn(a, b);
    return *reinterpret_cast<uint32_t*>(&h);
}

__device__ __forceinline__ void mma_f16(
    float& d0, float& d1, float& d2, float& d3,
    uint32_t a0, uint32_t a1, uint32_t a2, uint32_t a3,
    uint32_t b0, uint32_t b1)
{
    asm volatile(
        "mma.sync.aligned.m16n8k16.row.col.f32.f16.f16.f32 "
        "{%0,%1,%2,%3}, {%4,%5,%6,%7}, {%8,%9}, {%0,%1,%2,%3};\n"
        : "+f"(d0), "+f"(d1), "+f"(d2), "+f"(d3)
        : "r"(a0), "r"(a1), "r"(a2), "r"(a3), "r"(b0), "r"(b1));
}

__device__ __forceinline__ void ldsm_x4(
    uint32_t& r0, uint32_t& r1, uint32_t& r2, uint32_t& r3, uint32_t addr)
{
    asm volatile("ldmatrix.sync.aligned.m8n8.x4.shared.b16 {%0,%1,%2,%3}, [%4];"
                 : "=r"(r0), "=r"(r1), "=r"(r2), "=r"(r3) : "r"(addr));
}
__device__ __forceinline__ void ldsm_x4_t(
    uint32_t& r0, uint32_t& r1, uint32_t& r2, uint32_t& r3, uint32_t addr)
{
    asm volatile("ldmatrix.sync.aligned.m8n8.x4.trans.shared.b16 {%0,%1,%2,%3}, [%4];"
                 : "=r"(r0), "=r"(r1), "=r"(r2), "=r"(r3) : "r"(addr));
}

__device__ __forceinline__ void cp16(uint32_t saddr, const void* gptr) {
    asm volatile("cp.async.cg.shared.global [%0], [%1], 16;\n"
                 :: "r"(saddr), "l"(gptr));
}
#define CP_COMMIT() asm volatile("cp.async.commit_group;\n" ::: "memory")
#define CP_WAIT1()  asm volatile("cp.async.wait_group 1;\n" ::: "memory")
#define CP_WAIT0()  asm volatile("cp.async.wait_group 0;\n" ::: "memory")

// ================= fp32 -> fp16 pre-convert =================================
#define NX (BATCH * SEQ * DM)
#define NW (DM * DM)

__global__ __launch_bounds__(256) void cvt_kernel(
    const float* __restrict__ x,
    const float* __restrict__ wq,
    const float* __restrict__ wk,
    const float* __restrict__ wv,
    const float* __restrict__ wo)
{
    const size_t base = ((size_t)blockIdx.x * 256 + threadIdx.x) * 8;
    const float* src;
    __half* dst;
    size_t off;
    if (base < NX)               { src = x;  dst = g_xh;  off = base; }
    else if (base < NX + NW)     { src = wq; dst = g_Wqh; off = base - NX; }
    else if (base < NX + 2 * NW) { src = wk; dst = g_Wkh; off = base - NX - NW; }
    else if (base < NX + 3 * NW) { src = wv; dst = g_Wvh; off = base - NX - 2 * NW; }
    else                         { src = wo; dst = g_Woh; off = base - NX - 3 * NW; }

    float4 f0 = *(const float4*)(src + off);
    float4 f1 = *(const float4*)(src + off + 4);
    uint4 o;
    o.x = f2h2u(f0.x, f0.y); o.y = f2h2u(f0.z, f0.w);
    o.z = f2h2u(f1.x, f1.y); o.w = f2h2u(f1.z, f1.w);
    *(uint4*)(dst + off) = o;
}

// ============== fp16 GEMM: 128x128x32, cp.async 3-stage + ldmatrix ==========
#define TBM 128
#define TBN 128
#define TBK 32
#define ASTRIDE 40                       // halves per A row (32 data + 8 pad)
#define BSTRIDE 136                      // halves per B row (128 data + 8 pad)
#define A_BYTES (128 * ASTRIDE * 2)      // 10240
#define B_BYTES (32 * BSTRIDE * 2)       // 8704
#define STAGE_BYTES (A_BYTES + B_BYTES)  // 18944
#define GEMM_SMEM (3 * STAGE_BYTES)      // 56832

// A [M,K] fp16 row-major; W [K,N] fp16 row-major. Computes acc[4][4][4].
#define GEMM_BODY(A_, W_)                                                      \
    extern __shared__ __half smg[];                                            \
    const uint32_t sbase = (uint32_t)__cvta_generic_to_shared(smg);            \
    const int m0 = blockIdx.y * TBM;                                           \
    const int n0 = blockIdx.x * TBN;                                           \
    const int tid  = threadIdx.x;                                              \
    const int lane = tid & 31;                                                 \
    const int wid  = tid >> 5;                                                 \
    const int wm = wid >> 2;                                                   \
    const int wn = wid & 3;                                                    \
    const int lr = lane >> 2;                                                  \
    const int lc = lane & 3;                                                   \
    const int q8 = lane >> 3, r8 = lane & 7;                                   \
    uint32_t aoff[4], boff[2];                                                 \
    _Pragma("unroll")                                                          \
    for (int mf = 0; mf < 4; mf++)                                             \
        aoff[mf] = ((wm * 64 + mf * 16 + (q8 & 1) * 8 + r8) * ASTRIDE          \
                    + (q8 >> 1) * 8) * 2;                                      \
    _Pragma("unroll")                                                          \
    for (int pr = 0; pr < 2; pr++)                                             \
        boff[pr] = (((q8 & 1) * 8 + r8) * BSTRIDE                              \
                    + wn * 32 + pr * 16 + (q8 >> 1) * 8) * 2;                  \
    const int ar = tid >> 2, ac = tid & 3;                                     \
    const int br = tid >> 4, bc = tid & 15;                                    \
    float acc[4][4][4];                                                        \
    _Pragma("unroll")                                                          \
    for (int i = 0; i < 4; i++)                                                \
        _Pragma("unroll")                                                      \
        for (int j = 0; j < 4; j++)                                            \
            _Pragma("unroll")                                                  \
            for (int r = 0; r < 4; r++) acc[i][j][r] = 0.f;                    \
    auto issue = [&](int kt, int s) {                                          \
        const uint32_t ab = sbase + s * STAGE_BYTES;                           \
        const uint32_t bb = ab + A_BYTES;                                      \
        const int k0 = kt * TBK;                                               \
        cp16(ab + (ar * ASTRIDE + ac * 8) * 2,                                 \
             A_ + (size_t)(m0 + ar) * DM + k0 + ac * 8);                       \
        cp16(ab + ((ar + 64) * ASTRIDE + ac * 8) * 2,                          \
             A_ + (size_t)(m0 + ar + 64) * DM + k0 + ac * 8);                  \
        cp16(bb + (br * BSTRIDE + bc * 8) * 2,                                 \
             W_ + (size_t)(k0 + br) * DM + n0 + bc * 8);                       \
        cp16(bb + ((br + 16) * BSTRIDE + bc * 8) * 2,                          \
             W_ + (size_t)(k0 + br + 16) * DM + n0 + bc * 8);                  \
        CP_COMMIT();                                                           \
    };                                                                         \
    issue(0, 0);                                                               \
    issue(1, 1);                                                               \
    const int NT = DM / TBK;   /* 32 */                                        \
    for (int kt = 0; kt < NT; kt++) {                                          \
        const int s = kt % 3;                                                  \
        if (kt + 1 < NT) { CP_WAIT1(); } else { CP_WAIT0(); }                  \
        __syncthreads();                                                       \
        if (kt + 2 < NT) issue(kt + 2, (kt + 2) % 3);                          \
        const uint32_t ab = sbase + s * STAGE_BYTES;                           \
        const uint32_t bb = ab + A_BYTES;                                      \
        _Pragma("unroll")                                                      \
        for (int ks = 0; ks < 2; ks++) {                                       \
            uint32_t af[4][4], bf[4][2];                                       \
            _Pragma("unroll")                                                  \
            for (int mf = 0; mf < 4; mf++)                                     \
                ldsm_x4(af[mf][0], af[mf][1], af[mf][2], af[mf][3],            \
                        ab + aoff[mf] + ks * 32);                              \
            ldsm_x4_t(bf[0][0], bf[0][1], bf[1][0], bf[1][1],                  \
                      bb + boff[0] + ks * (16 * BSTRIDE * 2));                 \
            ldsm_x4_t(bf[2][0], bf[2][1], bf[3][0], bf[3][1],                  \
                      bb + boff[1] + ks * (16 * BSTRIDE * 2));                 \
            _Pragma("unroll")                                                  \
            for (int mf = 0; mf < 4; mf++)                                     \
                _Pragma("unroll")                                              \
                for (int nf = 0; nf < 4; nf++)                                 \
                    mma_f16(acc[mf][nf][0], acc[mf][nf][1],                    \
                            acc[mf][nf][2], acc[mf][nf][3],                    \
                            af[mf][0], af[mf][1], af[mf][2], af[mf][3],        \
                            bf[nf][0], bf[nf][1]);                             \
        }                                                                      \
    }

// ============ QKV GEMM: fused RoPE epilogue =================================
__global__ __launch_bounds__(256) void gemm_qkv_kernel(const int* __restrict__ pos)
{
    const int z = blockIdx.z;
    const __half* __restrict__ W =
        (z == 0) ? g_Wqh : (z == 1) ? g_Wkh : g_Wvh;
    __half* __restrict__ dsth = (z == 0) ? g_Qh : (z == 1) ? g_Kh : g_Vh;
    const __half* __restrict__ A = g_xh;

    GEMM_BODY(A, W)

    const int rb = m0 + wm * 64 + lr;
    const int cb = n0 + wn * 32 + 2 * lc;

    float invf[4];
    #pragma unroll
    for (int nf = 0; nf < 4; nf++) {
        const int d = (cb + nf * 8) & 63;
        invf[nf] = 1.0f / powf(10000.0f, (float)d / 64.0f);
    }
    const float qscale = (z == 0) ? 0.125f : 1.0f;

    #pragma unroll
    for (int mf = 0; mf < 4; mf++) {
        #pragma unroll
        for (int half = 0; half < 2; half++) {
            const int m = rb + mf * 16 + half * 8;
            const int b_ = m >> 11, s_ = m & (SEQ - 1);
            const float p = (float)pos[b_ * SEQ + s_];
            #pragma unroll
            for (int nf = 0; nf < 4; nf++) {
                const int n = cb + nf * 8;
                const int h = n >> 6, d = n & 63;
                const float ve = acc[mf][nf][half * 2];
                const float vo = acc[mf][nf][half * 2 + 1];
                float re, ro;
                if (z < 2) {
                    float sn, cs;
                    sincosf(p * invf[nf], &sn, &cs);
                    re = (ve * cs - vo * sn) * qscale;
                    ro = (ve * sn + vo * cs) * qscale;
                } else {
                    re = ve; ro = vo;
                }
                __half2* dp = (__half2*)(dsth + (((size_t)(b_ * NH + h)) * SEQ + s_) * DK + d);
                *dp = __floats2half2_rn(re, ro);
            }
        }
    }
}

// ============ WO GEMM ========================================================
__global__ __launch_bounds__(256) void gemm_out_kernel(float* __restrict__ out)
{
    const __half* __restrict__ A = g_Oh;
    const __half* __restrict__ W = g_Woh;

    GEMM_BODY(A, W)

    const int rb = m0 + wm * 64 + lr;
    const int cb = n0 + wn * 32 + 2 * lc;
    #pragma unroll
    for (int mf = 0; mf < 4; mf++) {
        #pragma unroll
        for (int nf = 0; nf < 4; nf++) {
            const int n = cb + nf * 8;
            #pragma unroll
            for (int half = 0; half < 2; half++) {
                const int m = rb + mf * 16 + half * 8;
                *(float2*)(out + (size_t)m * DM + n) =
                    make_float2(acc[mf][nf][half * 2], acc[mf][nf][half * 2 + 1]);
            }
        }
    }
}

// ================= fp16 flash attention (unchanged) =========================
#define FBM 64
#define FBN 64
#define QP2 36
#define KP2 72
#define VP2 72

__global__ __launch_bounds__(128) void flash_f16_kernel()
{
    __shared__ __half2 Qs[FBM * QP2];
    __shared__ __half2 Ks[(DK / 2) * KP2];
    __shared__ __half2 Vs[(FBN / 2) * VP2];

    const int bh = blockIdx.y;
    const int m0 = ((int)gridDim.x - 1 - (int)blockIdx.x) * FBM;
    const int tid  = threadIdx.x;
    const int lane = tid & 31;
    const int w    = tid >> 5;
    const int lr   = lane >> 2;
    const int lc   = lane & 3;

    const __half* __restrict__ Qb = g_Qh + (size_t)bh * SEQ * DK;
    const __half2* __restrict__ Kb2 = (const __half2*)(g_Kh + (size_t)bh * SEQ * DK);
    const __half* __restrict__ Vb = g_Vh + (size_t)bh * SEQ * DK;

    #pragma unroll
    for (int it = 0; it < 4; it++) {
        const int idx = tid + it * 128;
        const int row = idx >> 3, dq = idx & 7;
        *(uint4*)&Qs[row * QP2 + dq * 4] =
            *(const uint4*)(Qb + (size_t)(m0 + row) * DK + dq * 8);
    }
    __syncthreads();

    uint32_t qf[4][4];
    #pragma unroll
    for (int ks = 0; ks < 4; ks++) {
        const int r = w * 16 + lr;
        qf[ks][0] = h2u(Qs[(r    ) * QP2 + ks * 8 + lc    ]);
        qf[ks][1] = h2u(Qs[(r + 8) * QP2 + ks * 8 + lc    ]);
        qf[ks][2] = h2u(Qs[(r    ) * QP2 + ks * 8 + lc + 4]);
        qf[ks][3] = h2u(Qs[(r + 8) * QP2 + ks * 8 + lc + 4]);
    }

    float o[8][4];
    #pragma unroll
    for (int n = 0; n < 8; n++)
        #pragma unroll
        for (int c = 0; c < 4; c++) o[n][c] = 0.f;
    float mrow0 = -1e30f, mrow1 = -1e30f, lrow0 = 0.f, lrow1 = 0.f;

    const int nt = m0 / FBN + 1;
    for (int t = 0; t < nt; t++) {
        const int j0 = t * FBN;
        __syncthreads();

        #pragma unroll
        for (int it = 0; it < 4; it++) {
            const int idx = tid + it * 128;
            const int jg = idx >> 5, dp = idx & 31;
            #pragma unroll
            for (int i = 0; i < 4; i++)
                Ks[dp * KP2 + jg * 4 + i] = Kb2[(size_t)(j0 + jg * 4 + i) * 32 + dp];
        }
        #pragma unroll
        for (int it = 0; it < 4; it++) {
            const int idx = tid + it * 128;
            const int jp = idx >> 4, dq2 = idx & 15;
            uint2 u0 = *(const uint2*)(Vb + (size_t)(j0 + 2 * jp    ) * DK + dq2 * 4);
            uint2 u1 = *(const uint2*)(Vb + (size_t)(j0 + 2 * jp + 1) * DK + dq2 * 4);
            __half2 a0 = *(__half2*)&u0.x, a1 = *(__half2*)&u0.y;
            __half2 c0 = *(__half2*)&u1.x, c1 = *(__half2*)&u1.y;
            Vs[jp * VP2 + dq2 * 4 + 0] = __lows2half2 (a0, c0);
            Vs[jp * VP2 + dq2 * 4 + 1] = __highs2half2(a0, c0);
            Vs[jp * VP2 + dq2 * 4 + 2] = __lows2half2 (a1, c1);
            Vs[jp * VP2 + dq2 * 4 + 3] = __highs2half2(a1, c1);
        }
        __syncthreads();

        float s[8][4];
        #pragma unroll
        for (int n = 0; n < 8; n++)
            #pragma unroll
            for (int c = 0; c < 4; c++) s[n][c] = 0.f;

        #pragma unroll
        for (int ks = 0; ks < 4; ks++) {
            #pragma unroll
            for (int n = 0; n < 8; n++) {
                const int c = n * 8 + lr;
                const uint32_t b0 = h2u(Ks[(ks * 8 + lc    ) * KP2 + c]);
                const uint32_t b1 = h2u(Ks[(ks * 8 + lc + 4) * KP2 + c]);
                mma_f16(s[n][0], s[n][1], s[n][2], s[n][3],
                        qf[ks][0], qf[ks][1], qf[ks][2], qf[ks][3], b0, b1);
            }
        }

        if (t == nt - 1) {
            const int r0 = w * 16 + lr;
            #pragma unroll
            for (int n = 0; n < 8; n++) {
                const int c0 = n * 8 + 2 * lc;
                if (c0     > r0)     s[n][0] = -1e30f;
                if (c0 + 1 > r0)     s[n][1] = -1e30f;
                if (c0     > r0 + 8) s[n][2] = -1e30f;
                if (c0 + 1 > r0 + 8) s[n][3] = -1e30f;
            }
        }

        float mx0 = -1e30f, mx1 = -1e30f;
        #pragma unroll
        for (int n = 0; n < 8; n++) {
            mx0 = fmaxf(mx0, fmaxf(s[n][0], s[n][1]));
            mx1 = fmaxf(mx1, fmaxf(s[n][2], s[n][3]));
        }
        mx0 = fmaxf(mx0, __shfl_xor_sync(0xffffffffu, mx0, 1));
        mx0 = fmaxf(mx0, __shfl_xor_sync(0xffffffffu, mx0, 2));
        mx1 = fmaxf(mx1, __shfl_xor_sync(0xffffffffu, mx1, 1));
        mx1 = fmaxf(mx1, __shfl_xor_sync(0xffffffffu, mx1, 2));

        const float mn0 = fmaxf(mrow0, mx0);
        const float mn1 = fmaxf(mrow1, mx1);
        const float sc0 = __expf(mrow0 - mn0);
        const float sc1 = __expf(mrow1 - mn1);
        lrow0 *= sc0; lrow1 *= sc1;
        #pragma unroll
        for (int n = 0; n < 8; n++) {
            o[n][0] *= sc0; o[n][1] *= sc0;
            o[n][2] *= sc1; o[n][3] *= sc1;
        }
        mrow0 = mn0; mrow1 = mn1;

        uint32_t pv[8][2];
        #pragma unroll
        for (int n = 0; n < 8; n++) {
            const float p0 = __expf(s[n][0] - mn0);
            const float p1 = __expf(s[n][1] - mn0);
            const float p2 = __expf(s[n][2] - mn1);
            const float p3 = __expf(s[n][3] - mn1);
            lrow0 += p0 + p1;
            lrow1 += p2 + p3;
            pv[n][0] = f2h2u(p0, p1);
            pv[n][1] = f2h2u(p2, p3);
        }

        #pragma unroll
        for (int ks = 0; ks < 4; ks++) {
            const uint32_t a0 = pv[2 * ks    ][0];
            const uint32_t a1 = pv[2 * ks    ][1];
            const uint32_t a2 = pv[2 * ks + 1][0];
            const uint32_t a3 = pv[2 * ks + 1][1];
            #pragma unroll
            for (int n = 0; n < 8; n++) {
                const int c = n * 8 + lr;
                const uint32_t b0 = h2u(Vs[(ks * 8 + lc    ) * VP2 + c]);
                const uint32_t b1 = h2u(Vs[(ks * 8 + lc + 4) * VP2 + c]);
                mma_f16(o[n][0], o[n][1], o[n][2], o[n][3], a0, a1, a2, a3, b0, b1);
            }
        }
    }

    lrow0 += __shfl_xor_sync(0xffffffffu, lrow0, 1);
    lrow0 += __shfl_xor_sync(0xffffffffu, lrow0, 2);
    lrow1 += __shfl_xor_sync(0xffffffffu, lrow1, 1);
    lrow1 += __shfl_xor_sync(0xffffffffu, lrow1, 2);
    const float inv0 = 1.0f / lrow0;
    const float inv1 = 1.0f / lrow1;

    const int b_ = bh >> 4, h = bh & 15;
    const int r0 = m0 + w * 16 + lr;
    const int r1 = r0 + 8;
    #pragma unroll
    for (int n = 0; n < 8; n++) {
        const int d = h * 64 + n * 8 + 2 * lc;
        *(__half2*)(g_Oh + ((size_t)b_ * SEQ + r0) * DM + d) =
            __floats2half2_rn(o[n][0] * inv0, o[n][1] * inv0);
        *(__half2*)(g_Oh + ((size_t)b_ * SEQ + r1) * DM + d) =
            __floats2half2_rn(o[n][2] * inv1, o[n][3] * inv1);
    }
}

// ---------------- launch ----------------------------------------------------
extern "C" void kernel_launch(void* const* d_in, const int* in_sizes, int n_in,
                              void* d_out, int out_size)
{
    (void)in_sizes; (void)n_in; (void)out_size;
    const float* x   = (const float*)d_in[0];
    const int*   pos = (const int*)  d_in[1];
    const float* WQ  = (const float*)d_in[2];
    const float* WK  = (const float*)d_in[3];
    const float* WV  = (const float*)d_in[4];
    const float* WO  = (const float*)d_in[5];
    float* out = (float*)d_out;

    cudaFuncSetAttribute(gemm_qkv_kernel,
                         cudaFuncAttributeMaxDynamicSharedMemorySize, GEMM_SMEM);
    cudaFuncSetAttribute(gemm_out_kernel,
                         cudaFuncAttributeMaxDynamicSharedMemorySize, GEMM_SMEM);

    const int ncvt = (NX + 4 * NW) / (8 * 256);
    cvt_kernel<<<ncvt, 256>>>(x, WQ, WK, WV, WO);

    dim3 gq(DM / TBN, (BATCH * SEQ) / TBM, 3);      // (8, 32, 3)
    gemm_qkv_kernel<<<gq, 256, GEMM_SMEM>>>(pos);

    dim3 gf(SEQ / FBM, BATCH * NH);                 // (32, 32)
    flash_f16_kernel<<<gf, 128>>>();

    dim3 go(DM / TBN, (BATCH * SEQ) / TBM, 1);      // (8, 32)
    gemm_out_kernel<<<go, 256, GEMM_SMEM>>>(out);
}

// round 11
// speedup vs baseline: 2.1082x; 1.0050x over previous
#include <cuda_runtime.h>
#include <cuda_fp16.h>
#include <math.h>
#include <stdint.h>

#define BATCH 2
#define SEQ   2048
#define DM    1024
#define NH    16
#define DK    64

// fp16 scratch (device globals; no allocation allowed)
__device__ __half g_xh[BATCH * SEQ * DM];
__device__ __half g_Wqh[DM * DM];
__device__ __half g_Wkh[DM * DM];
__device__ __half g_Wvh[DM * DM];
__device__ __half g_Woh[DM * DM];
__device__ __half g_Qh[BATCH * NH * SEQ * DK];   // roped, x0.125
__device__ __half g_Kh[BATCH * NH * SEQ * DK];   // roped
__device__ __half g_Vh[BATCH * NH * SEQ * DK];
__device__ __half g_Oh[BATCH * SEQ * DM];

__device__ __forceinline__ uint32_t h2u(__half2 h) {
    return *reinterpret_cast<uint32_t*>(&h);
}
__device__ __forceinline__ uint32_t f2h2u(float a, float b) {
    __half2 h = __floats2half2_rn(a, b);
    return *reinterpret_cast<uint32_t*>(&h);
}

__device__ __forceinline__ void mma_f16(
    float& d0, float& d1, float& d2, float& d3,
    uint32_t a0, uint32_t a1, uint32_t a2, uint32_t a3,
    uint32_t b0, uint32_t b1)
{
    asm volatile(
        "mma.sync.aligned.m16n8k16.row.col.f32.f16.f16.f32 "
        "{%0,%1,%2,%3}, {%4,%5,%6,%7}, {%8,%9}, {%0,%1,%2,%3};\n"
        : "+f"(d0), "+f"(d1), "+f"(d2), "+f"(d3)
        : "r"(a0), "r"(a1), "r"(a2), "r"(a3), "r"(b0), "r"(b1));
}

__device__ __forceinline__ void ldsm_x4(
    uint32_t& r0, uint32_t& r1, uint32_t& r2, uint32_t& r3, uint32_t addr)
{
    asm volatile("ldmatrix.sync.aligned.m8n8.x4.shared.b16 {%0,%1,%2,%3}, [%4];"
                 : "=r"(r0), "=r"(r1), "=r"(r2), "=r"(r3) : "r"(addr));
}
__device__ __forceinline__ void ldsm_x4_t(
    uint32_t& r0, uint32_t& r1, uint32_t& r2, uint32_t& r3, uint32_t addr)
{
    asm volatile("ldmatrix.sync.aligned.m8n8.x4.trans.shared.b16 {%0,%1,%2,%3}, [%4];"
                 : "=r"(r0), "=r"(r1), "=r"(r2), "=r"(r3) : "r"(addr));
}

__device__ __forceinline__ void cp16(uint32_t saddr, const void* gptr) {
    asm volatile("cp.async.cg.shared.global [%0], [%1], 16;\n"
                 :: "r"(saddr), "l"(gptr));
}
#define CP_COMMIT() asm volatile("cp.async.commit_group;\n" ::: "memory")
#define CP_WAIT2()  asm volatile("cp.async.wait_group 2;\n" ::: "memory")
#define CP_WAIT1()  asm volatile("cp.async.wait_group 1;\n" ::: "memory")
#define CP_WAIT0()  asm volatile("cp.async.wait_group 0;\n" ::: "memory")

// ================= fp32 -> fp16 pre-convert =================================
#define NX (BATCH * SEQ * DM)
#define NW (DM * DM)

__global__ __launch_bounds__(256) void cvt_kernel(
    const float* __restrict__ x,
    const float* __restrict__ wq,
    const float* __restrict__ wk,
    const float* __restrict__ wv,
    const float* __restrict__ wo)
{
    const size_t base = ((size_t)blockIdx.x * 256 + threadIdx.x) * 8;
    const float* src;
    __half* dst;
    size_t off;
    if (base < NX)               { src = x;  dst = g_xh;  off = base; }
    else if (base < NX + NW)     { src = wq; dst = g_Wqh; off = base - NX; }
    else if (base < NX + 2 * NW) { src = wk; dst = g_Wkh; off = base - NX - NW; }
    else if (base < NX + 3 * NW) { src = wv; dst = g_Wvh; off = base - NX - 2 * NW; }
    else                         { src = wo; dst = g_Woh; off = base - NX - 3 * NW; }

    float4 f0 = *(const float4*)(src + off);
    float4 f1 = *(const float4*)(src + off + 4);
    uint4 o;
    o.x = f2h2u(f0.x, f0.y); o.y = f2h2u(f0.z, f0.w);
    o.z = f2h2u(f1.x, f1.y); o.w = f2h2u(f1.z, f1.w);
    *(uint4*)(dst + off) = o;
}

// ============== fp16 GEMM: 128x128x32, cp.async 4-stage + ldmatrix ==========
#define TBM 128
#define TBN 128
#define TBK 32
#define ASTRIDE 40
#define BSTRIDE 136
#define A_BYTES (128 * ASTRIDE * 2)
#define B_BYTES (32 * BSTRIDE * 2)
#define STAGE_BYTES (A_BYTES + B_BYTES)  // 18944
#define NSTAGE 4
#define GEMM_SMEM (NSTAGE * STAGE_BYTES) // 75776

#define GEMM_BODY(A_, W_)                                                      \
    extern __shared__ __half smg[];                                            \
    const uint32_t sbase = (uint32_t)__cvta_generic_to_shared(smg);            \
    const int m0 = blockIdx.y * TBM;                                           \
    const int n0 = blockIdx.x * TBN;                                           \
    const int tid  = threadIdx.x;                                              \
    const int lane = tid & 31;                                                 \
    const int wid  = tid >> 5;                                                 \
    const int wm = wid >> 2;                                                   \
    const int wn = wid & 3;                                                    \
    const int lr = lane >> 2;                                                  \
    const int lc = lane & 3;                                                   \
    const int q8 = lane >> 3, r8 = lane & 7;                                   \
    uint32_t aoff[4], boff[2];                                                 \
    _Pragma("unroll")                                                          \
    for (int mf = 0; mf < 4; mf++)                                             \
        aoff[mf] = ((wm * 64 + mf * 16 + (q8 & 1) * 8 + r8) * ASTRIDE          \
                    + (q8 >> 1) * 8) * 2;                                      \
    _Pragma("unroll")                                                          \
    for (int pr = 0; pr < 2; pr++)                                             \
        boff[pr] = (((q8 & 1) * 8 + r8) * BSTRIDE                              \
                    + wn * 32 + pr * 16 + (q8 >> 1) * 8) * 2;                  \
    const int ar = tid >> 2, ac = tid & 3;                                     \
    const int br = tid >> 4, bc = tid & 15;                                    \
    float acc[4][4][4];                                                        \
    _Pragma("unroll")                                                          \
    for (int i = 0; i < 4; i++)                                                \
        _Pragma("unroll")                                                      \
        for (int j = 0; j < 4; j++)                                            \
            _Pragma("unroll")                                                  \
            for (int r = 0; r < 4; r++) acc[i][j][r] = 0.f;                    \
    auto issue = [&](int kt, int s) {                                          \
        const uint32_t ab = sbase + s * STAGE_BYTES;                           \
        const uint32_t bb = ab + A_BYTES;                                      \
        const int k0 = kt * TBK;                                               \
        cp16(ab + (ar * ASTRIDE + ac * 8) * 2,                                 \
             A_ + (size_t)(m0 + ar) * DM + k0 + ac * 8);                       \
        cp16(ab + ((ar + 64) * ASTRIDE + ac * 8) * 2,                          \
             A_ + (size_t)(m0 + ar + 64) * DM + k0 + ac * 8);                  \
        cp16(bb + (br * BSTRIDE + bc * 8) * 2,                                 \
             W_ + (size_t)(k0 + br) * DM + n0 + bc * 8);                       \
        cp16(bb + ((br + 16) * BSTRIDE + bc * 8) * 2,                          \
             W_ + (size_t)(k0 + br + 16) * DM + n0 + bc * 8);                  \
        CP_COMMIT();                                                           \
    };                                                                         \
    issue(0, 0);                                                               \
    issue(1, 1);                                                               \
    issue(2, 2);                                                               \
    const int NT = DM / TBK;   /* 32 */                                        \
    for (int kt = 0; kt < NT; kt++) {                                          \
        const int s = kt & 3;                                                  \
        if (kt + 2 < NT)      { CP_WAIT2(); }                                  \
        else if (kt + 1 < NT) { CP_WAIT1(); }                                  \
        else                  { CP_WAIT0(); }                                  \
        __syncthreads();                                                       \
        if (kt + 3 < NT) issue(kt + 3, (kt + 3) & 3);                          \
        const uint32_t ab = sbase + s * STAGE_BYTES;                           \
        const uint32_t bb = ab + A_BYTES;                                      \
        _Pragma("unroll")                                                      \
        for (int ks = 0; ks < 2; ks++) {                                       \
            uint32_t af[4][4], bf[4][2];                                       \
            _Pragma("unroll")                                                  \
            for (int mf = 0; mf < 4; mf++)                                     \
                ldsm_x4(af[mf][0], af[mf][1], af[mf][2], af[mf][3],            \
                        ab + aoff[mf] + ks * 32);                              \
            ldsm_x4_t(bf[0][0], bf[0][1], bf[1][0], bf[1][1],                  \
                      bb + boff[0] + ks * (16 * BSTRIDE * 2));                 \
            ldsm_x4_t(bf[2][0], bf[2][1], bf[3][0], bf[3][1],                  \
                      bb + boff[1] + ks * (16 * BSTRIDE * 2));                 \
            _Pragma("unroll")                                                  \
            for (int mf = 0; mf < 4; mf++)                                     \
                _Pragma("unroll")                                              \
                for (int nf = 0; nf < 4; nf++)                                 \
                    mma_f16(acc[mf][nf][0], acc[mf][nf][1],                    \
                            acc[mf][nf][2], acc[mf][nf][3],                    \
                            af[mf][0], af[mf][1], af[mf][2], af[mf][3],        \
                            bf[nf][0], bf[nf][1]);                             \
        }                                                                      \
    }

// ============ QKV GEMM: fused RoPE epilogue =================================
__global__ __launch_bounds__(256) void gemm_qkv_kernel(const int* __restrict__ pos)
{
    const int z = blockIdx.z;
    const __half* __restrict__ W =
        (z == 0) ? g_Wqh : (z == 1) ? g_Wkh : g_Wvh;
    __half* __restrict__ dsth = (z == 0) ? g_Qh : (z == 1) ? g_Kh : g_Vh;
    const __half* __restrict__ A = g_xh;

    GEMM_BODY(A, W)

    const int rb = m0 + wm * 64 + lr;
    const int cb = n0 + wn * 32 + 2 * lc;

    float invf[4];
    #pragma unroll
    for (int nf = 0; nf < 4; nf++) {
        const int d = (cb + nf * 8) & 63;
        invf[nf] = 1.0f / powf(10000.0f, (float)d / 64.0f);
    }
    const float qscale = (z == 0) ? 0.125f : 1.0f;

    #pragma unroll
    for (int mf = 0; mf < 4; mf++) {
        #pragma unroll
        for (int half = 0; half < 2; half++) {
            const int m = rb + mf * 16 + half * 8;
            const int b_ = m >> 11, s_ = m & (SEQ - 1);
            const float p = (float)pos[b_ * SEQ + s_];
            #pragma unroll
            for (int nf = 0; nf < 4; nf++) {
                const int n = cb + nf * 8;
                const int h = n >> 6, d = n & 63;
                const float ve = acc[mf][nf][half * 2];
                const float vo = acc[mf][nf][half * 2 + 1];
                float re, ro;
                if (z < 2) {
                    float sn, cs;
                    sincosf(p * invf[nf], &sn, &cs);
                    re = (ve * cs - vo * sn) * qscale;
                    ro = (ve * sn + vo * cs) * qscale;
                } else {
                    re = ve; ro = vo;
                }
                __half2* dp = (__half2*)(dsth + (((size_t)(b_ * NH + h)) * SEQ + s_) * DK + d);
                *dp = __floats2half2_rn(re, ro);
            }
        }
    }
}

// ============ WO GEMM ========================================================
__global__ __launch_bounds__(256) void gemm_out_kernel(float* __restrict__ out)
{
    const __half* __restrict__ A = g_Oh;
    const __half* __restrict__ W = g_Woh;

    GEMM_BODY(A, W)

    const int rb = m0 + wm * 64 + lr;
    const int cb = n0 + wn * 32 + 2 * lc;
    #pragma unroll
    for (int mf = 0; mf < 4; mf++) {
        #pragma unroll
        for (int nf = 0; nf < 4; nf++) {
            const int n = cb + nf * 8;
            #pragma unroll
            for (int half = 0; half < 2; half++) {
                const int m = rb + mf * 16 + half * 8;
                *(float2*)(out + (size_t)m * DM + n) =
                    make_float2(acc[mf][nf][half * 2], acc[mf][nf][half * 2 + 1]);
            }
        }
    }
}

// ================= fp16 flash attention: FBM=64, FBN=128 ====================
#define FBM 64
#define FBN 128
#define QP2 36
#define KP2 136   // j width 128 + 8 pad (half2 units)
#define VP2 72    // d width 64 + 8 pad (half2 units)

__global__ __launch_bounds__(128) void flash_f16_kernel()
{
    __shared__ __half2 Qs[FBM * QP2];          //  9216 B
    __shared__ __half2 Ks[(DK / 2) * KP2];     // 17408 B
    __shared__ __half2 Vs[(FBN / 2) * VP2];    // 18432 B

    const int bh = blockIdx.y;
    const int m0 = ((int)gridDim.x - 1 - (int)blockIdx.x) * FBM;
    const int tid  = threadIdx.x;
    const int lane = tid & 31;
    const int w    = tid >> 5;
    const int lr   = lane >> 2;
    const int lc   = lane & 3;

    const __half* __restrict__ Qb = g_Qh + (size_t)bh * SEQ * DK;
    const __half2* __restrict__ Kb2 = (const __half2*)(g_Kh + (size_t)bh * SEQ * DK);
    const __half* __restrict__ Vb = g_Vh + (size_t)bh * SEQ * DK;

    #pragma unroll
    for (int it = 0; it < 4; it++) {
        const int idx = tid + it * 128;
        const int row = idx >> 3, dq = idx & 7;
        *(uint4*)&Qs[row * QP2 + dq * 4] =
            *(const uint4*)(Qb + (size_t)(m0 + row) * DK + dq * 8);
    }
    __syncthreads();

    uint32_t qf[4][4];
    #pragma unroll
    for (int ks = 0; ks < 4; ks++) {
        const int r = w * 16 + lr;
        qf[ks][0] = h2u(Qs[(r    ) * QP2 + ks * 8 + lc    ]);
        qf[ks][1] = h2u(Qs[(r + 8) * QP2 + ks * 8 + lc    ]);
        qf[ks][2] = h2u(Qs[(r    ) * QP2 + ks * 8 + lc + 4]);
        qf[ks][3] = h2u(Qs[(r + 8) * QP2 + ks * 8 + lc + 4]);
    }

    float o[8][4];
    #pragma unroll
    for (int n = 0; n < 8; n++)
        #pragma unroll
        for (int c = 0; c < 4; c++) o[n][c] = 0.f;
    float mrow0 = -1e30f, mrow1 = -1e30f, lrow0 = 0.f, lrow1 = 0.f;

    const int gr_lo = m0 + w * 16;
    const int nt = m0 / FBN + 1;
    for (int t = 0; t < nt; t++) {
        const int j0 = t * FBN;
        __syncthreads();

        // K: Ks[dp][j] over j 0..127 (1024 half2, 8 iters)
        #pragma unroll
        for (int it = 0; it < 8; it++) {
            const int idx = tid + it * 128;
            const int jg = idx >> 5, dp = idx & 31;
            #pragma unroll
            for (int i = 0; i < 4; i++)
                Ks[dp * KP2 + jg * 4 + i] = Kb2[(size_t)(j0 + jg * 4 + i) * 32 + dp];
        }
        // V: Vs[jp][d], jp 0..63 (8 iters)
        #pragma unroll
        for (int it = 0; it < 8; it++) {
            const int idx = tid + it * 128;
            const int jp = idx >> 4, dq2 = idx & 15;
            uint2 u0 = *(const uint2*)(Vb + (size_t)(j0 + 2 * jp    ) * DK + dq2 * 4);
            uint2 u1 = *(const uint2*)(Vb + (size_t)(j0 + 2 * jp + 1) * DK + dq2 * 4);
            __half2 a0 = *(__half2*)&u0.x, a1 = *(__half2*)&u0.y;
            __half2 c0 = *(__half2*)&u1.x, c1 = *(__half2*)&u1.y;
            Vs[jp * VP2 + dq2 * 4 + 0] = __lows2half2 (a0, c0);
            Vs[jp * VP2 + dq2 * 4 + 1] = __highs2half2(a0, c0);
            Vs[jp * VP2 + dq2 * 4 + 2] = __lows2half2 (a1, c1);
            Vs[jp * VP2 + dq2 * 4 + 3] = __highs2half2(a1, c1);
        }
        __syncthreads();

        // ---- S = Q K^T : 16 n-frags over 128 cols ----
        float s[16][4];
        #pragma unroll
        for (int n = 0; n < 16; n++)
            #pragma unroll
            for (int c = 0; c < 4; c++) s[n][c] = 0.f;

        #pragma unroll
        for (int ks = 0; ks < 4; ks++) {
            #pragma unroll
            for (int n = 0; n < 16; n++) {
                const int c = n * 8 + lr;
                const uint32_t b0 = h2u(Ks[(ks * 8 + lc    ) * KP2 + c]);
                const uint32_t b1 = h2u(Ks[(ks * 8 + lc + 4) * KP2 + c]);
                mma_f16(s[n][0], s[n][1], s[n][2], s[n][3],
                        qf[ks][0], qf[ks][1], qf[ks][2], qf[ks][3], b0, b1);
            }
        }

        // ---- causal mask: only the last tile crosses the diagonal ----
        if (t == nt - 1) {
            const int r0 = gr_lo + lr;
            #pragma unroll
            for (int n = 0; n < 16; n++) {
                const int c0 = j0 + n * 8 + 2 * lc;
                if (c0     > r0)     s[n][0] = -1e30f;
                if (c0 + 1 > r0)     s[n][1] = -1e30f;
                if (c0     > r0 + 8) s[n][2] = -1e30f;
                if (c0 + 1 > r0 + 8) s[n][3] = -1e30f;
            }
        }

        float mx0 = -1e30f, mx1 = -1e30f;
        #pragma unroll
        for (int n = 0; n < 16; n++) {
            mx0 = fmaxf(mx0, fmaxf(s[n][0], s[n][1]));
            mx1 = fmaxf(mx1, fmaxf(s[n][2], s[n][3]));
        }
        mx0 = fmaxf(mx0, __shfl_xor_sync(0xffffffffu, mx0, 1));
        mx0 = fmaxf(mx0, __shfl_xor_sync(0xffffffffu, mx0, 2));
        mx1 = fmaxf(mx1, __shfl_xor_sync(0xffffffffu, mx1, 1));
        mx1 = fmaxf(mx1, __shfl_xor_sync(0xffffffffu, mx1, 2));

        const float mn0 = fmaxf(mrow0, mx0);
        const float mn1 = fmaxf(mrow1, mx1);
        const float sc0 = __expf(mrow0 - mn0);
        const float sc1 = __expf(mrow1 - mn1);
        lrow0 *= sc0; lrow1 *= sc1;
        #pragma unroll
        for (int n = 0; n < 8; n++) {
            o[n][0] *= sc0; o[n][1] *= sc0;
            o[n][2] *= sc1; o[n][3] *= sc1;
        }
        mrow0 = mn0; mrow1 = mn1;

        uint32_t pv[16][2];
        #pragma unroll
        for (int n = 0; n < 16; n++) {
            const float p0 = __expf(s[n][0] - mn0);
            const float p1 = __expf(s[n][1] - mn0);
            const float p2 = __expf(s[n][2] - mn1);
            const float p3 = __expf(s[n][3] - mn1);
            lrow0 += p0 + p1;
            lrow1 += p2 + p3;
            pv[n][0] = f2h2u(p0, p1);
            pv[n][1] = f2h2u(p2, p3);
        }

        // ---- O += P V : 8 k-steps over 128 j ----
        #pragma unroll
        for (int ks = 0; ks < 8; ks++) {
            const uint32_t a0 = pv[2 * ks    ][0];
            const uint32_t a1 = pv[2 * ks    ][1];
            const uint32_t a2 = pv[2 * ks + 1][0];
            const uint32_t a3 = pv[2 * ks + 1][1];
            #pragma unroll
            for (int n = 0; n < 8; n++) {
                const int c = n * 8 + lr;
                const uint32_t b0 = h2u(Vs[(ks * 8 + lc    ) * VP2 + c]);
                const uint32_t b1 = h2u(Vs[(ks * 8 + lc + 4) * VP2 + c]);
                mma_f16(o[n][0], o[n][1], o[n][2], o[n][3], a0, a1, a2, a3, b0, b1);
            }
        }
    }

    lrow0 += __shfl_xor_sync(0xffffffffu, lrow0, 1);
    lrow0 += __shfl_xor_sync(0xffffffffu, lrow0, 2);
    lrow1 += __shfl_xor_sync(0xffffffffu, lrow1, 1);
    lrow1 += __shfl_xor_sync(0xffffffffu, lrow1, 2);
    const float inv0 = 1.0f / lrow0;
    const float inv1 = 1.0f / lrow1;

    const int b_ = bh >> 4, h = bh & 15;
    const int r0 = m0 + w * 16 + lr;
    const int r1 = r0 + 8;
    #pragma unroll
    for (int n = 0; n < 8; n++) {
        const int d = h * 64 + n * 8 + 2 * lc;
        *(__half2*)(g_Oh + ((size_t)b_ * SEQ + r0) * DM + d) =
            __floats2half2_rn(o[n][0] * inv0, o[n][1] * inv0);
        *(__half2*)(g_Oh + ((size_t)b_ * SEQ + r1) * DM + d) =
            __floats2half2_rn(o[n][2] * inv1, o[n][3] * inv1);
    }
}

// ---------------- launch ----------------------------------------------------
extern "C" void kernel_launch(void* const* d_in, const int* in_sizes, int n_in,
                              void* d_out, int out_size)
{
    (void)in_sizes; (void)n_in; (void)out_size;
    const float* x   = (const float*)d_in[0];
    const int*   pos = (const int*)  d_in[1];
    const float* WQ  = (const float*)d_in[2];
    const float* WK  = (const float*)d_in[3];
    const float* WV  = (const float*)d_in[4];
    const float* WO  = (const float*)d_in[5];
    float* out = (float*)d_out;

    cudaFuncSetAttribute(gemm_qkv_kernel,
                         cudaFuncAttributeMaxDynamicSharedMemorySize, GEMM_SMEM);
    cudaFuncSetAttribute(gemm_out_kernel,
                         cudaFuncAttributeMaxDynamicSharedMemorySize, GEMM_SMEM);

    const int ncvt = (NX + 4 * NW) / (8 * 256);
    cvt_kernel<<<ncvt, 256>>>(x, WQ, WK, WV, WO);

    dim3 gq(DM / TBN, (BATCH * SEQ) / TBM, 3);      // (8, 32, 3)
    gemm_qkv_kernel<<<gq, 256, GEMM_SMEM>>>(pos);

    dim3 gf(SEQ / FBM, BATCH * NH);                 // (32, 32)
    flash_f16_kernel<<<gf, 128>>>();

    dim3 go(DM / TBN, (BATCH * SEQ) / TBM, 1);      // (8, 32)
    gemm_out_kernel<<<go, 256, GEMM_SMEM>>>(out);
}

// round 12
// speedup vs baseline: 2.3106x; 1.0960x over previous
#include <cuda_runtime.h>
#include <cuda_fp16.h>
#include <math.h>
#include <stdint.h>

#define BATCH 2
#define SEQ   2048
#define DM    1024
#define NH    16
#define DK    64

// fp16 scratch (device globals; no allocation allowed)
__device__ __half g_xh[BATCH * SEQ * DM];
__device__ __half g_Wqh[DM * DM];
__device__ __half g_Wkh[DM * DM];
__device__ __half g_Wvh[DM * DM];
__device__ __half g_Woh[DM * DM];
__device__ __half g_Qh[BATCH * NH * SEQ * DK];   // roped, x0.125
__device__ __half g_Kh[BATCH * NH * SEQ * DK];   // roped
__device__ __half g_Vh[BATCH * NH * SEQ * DK];
__device__ __half g_Oh[BATCH * SEQ * DM];

__device__ __forceinline__ uint32_t h2u(__half2 h) {
    return *reinterpret_cast<uint32_t*>(&h);
}
__device__ __forceinline__ uint32_t f2h2u(float a, float b) {
    __half2 h = __floats2half2_rn(a, b);
    return *reinterpret_cast<uint32_t*>(&h);
}

__device__ __forceinline__ void mma_f16(
    float& d0, float& d1, float& d2, float& d3,
    uint32_t a0, uint32_t a1, uint32_t a2, uint32_t a3,
    uint32_t b0, uint32_t b1)
{
    asm volatile(
        "mma.sync.aligned.m16n8k16.row.col.f32.f16.f16.f32 "
        "{%0,%1,%2,%3}, {%4,%5,%6,%7}, {%8,%9}, {%0,%1,%2,%3};\n"
        : "+f"(d0), "+f"(d1), "+f"(d2), "+f"(d3)
        : "r"(a0), "r"(a1), "r"(a2), "r"(a3), "r"(b0), "r"(b1));
}

__device__ __forceinline__ void ldsm_x4(
    uint32_t& r0, uint32_t& r1, uint32_t& r2, uint32_t& r3, uint32_t addr)
{
    asm volatile("ldmatrix.sync.aligned.m8n8.x4.shared.b16 {%0,%1,%2,%3}, [%4];"
                 : "=r"(r0), "=r"(r1), "=r"(r2), "=r"(r3) : "r"(addr));
}
__device__ __forceinline__ void ldsm_x4_t(
    uint32_t& r0, uint32_t& r1, uint32_t& r2, uint32_t& r3, uint32_t addr)
{
    asm volatile("ldmatrix.sync.aligned.m8n8.x4.trans.shared.b16 {%0,%1,%2,%3}, [%4];"
                 : "=r"(r0), "=r"(r1), "=r"(r2), "=r"(r3) : "r"(addr));
}

__device__ __forceinline__ void cp16(uint32_t saddr, const void* gptr) {
    asm volatile("cp.async.cg.shared.global [%0], [%1], 16;\n"
                 :: "r"(saddr), "l"(gptr));
}
#define CP_COMMIT() asm volatile("cp.async.commit_group;\n" ::: "memory")
#define CP_WAIT2()  asm volatile("cp.async.wait_group 2;\n" ::: "memory")
#define CP_WAIT1()  asm volatile("cp.async.wait_group 1;\n" ::: "memory")
#define CP_WAIT0()  asm volatile("cp.async.wait_group 0;\n" ::: "memory")

// ================= fp32 -> fp16 pre-convert =================================
#define NX (BATCH * SEQ * DM)
#define NW (DM * DM)

__global__ __launch_bounds__(256) void cvt_kernel(
    const float* __restrict__ x,
    const float* __restrict__ wq,
    const float* __restrict__ wk,
    const float* __restrict__ wv,
    const float* __restrict__ wo)
{
    const size_t base = ((size_t)blockIdx.x * 256 + threadIdx.x) * 8;
    const float* src;
    __half* dst;
    size_t off;
    if (base < NX)               { src = x;  dst = g_xh;  off = base; }
    else if (base < NX + NW)     { src = wq; dst = g_Wqh; off = base - NX; }
    else if (base < NX + 2 * NW) { src = wk; dst = g_Wkh; off = base - NX - NW; }
    else if (base < NX + 3 * NW) { src = wv; dst = g_Wvh; off = base - NX - 2 * NW; }
    else                         { src = wo; dst = g_Woh; off = base - NX - 3 * NW; }

    float4 f0 = *(const float4*)(src + off);
    float4 f1 = *(const float4*)(src + off + 4);
    uint4 o;
    o.x = f2h2u(f0.x, f0.y); o.y = f2h2u(f0.z, f0.w);
    o.z = f2h2u(f1.x, f1.y); o.w = f2h2u(f1.z, f1.w);
    *(uint4*)(dst + off) = o;
}

// ============== fp16 GEMM: 128x128x32, cp.async 4-stage + ldmatrix ==========
#define TBM 128
#define TBN 128
#define TBK 32
#define ASTRIDE 40
#define BSTRIDE 136
#define A_BYTES (128 * ASTRIDE * 2)
#define B_BYTES (32 * BSTRIDE * 2)
#define STAGE_BYTES (A_BYTES + B_BYTES)  // 18944
#define NSTAGE 4
#define GEMM_SMEM (NSTAGE * STAGE_BYTES) // 75776

#define GEMM_BODY(A_, W_)                                                      \
    extern __shared__ __half smg[];                                            \
    const uint32_t sbase = (uint32_t)__cvta_generic_to_shared(smg);            \
    const int m0 = blockIdx.y * TBM;                                           \
    const int n0 = blockIdx.x * TBN;                                           \
    const int tid  = threadIdx.x;                                              \
    const int lane = tid & 31;                                                 \
    const int wid  = tid >> 5;                                                 \
    const int wm = wid >> 2;                                                   \
    const int wn = wid & 3;                                                    \
    const int lr = lane >> 2;                                                  \
    const int lc = lane & 3;                                                   \
    const int q8 = lane >> 3, r8 = lane & 7;                                   \
    uint32_t aoff[4], boff[2];                                                 \
    _Pragma("unroll")                                                          \
    for (int mf = 0; mf < 4; mf++)                                             \
        aoff[mf] = ((wm * 64 + mf * 16 + (q8 & 1) * 8 + r8) * ASTRIDE          \
                    + (q8 >> 1) * 8) * 2;                                      \
    _Pragma("unroll")                                                          \
    for (int pr = 0; pr < 2; pr++)                                             \
        boff[pr] = (((q8 & 1) * 8 + r8) * BSTRIDE                              \
                    + wn * 32 + pr * 16 + (q8 >> 1) * 8) * 2;                  \
    const int ar = tid >> 2, ac = tid & 3;                                     \
    const int br = tid >> 4, bc = tid & 15;                                    \
    float acc[4][4][4];                                                        \
    _Pragma("unroll")                                                          \
    for (int i = 0; i < 4; i++)                                                \
        _Pragma("unroll")                                                      \
        for (int j = 0; j < 4; j++)                                            \
            _Pragma("unroll")                                                  \
            for (int r = 0; r < 4; r++) acc[i][j][r] = 0.f;                    \
    auto issue = [&](int kt, int s) {                                          \
        const uint32_t ab = sbase + s * STAGE_BYTES;                           \
        const uint32_t bb = ab + A_BYTES;                                      \
        const int k0 = kt * TBK;                                               \
        cp16(ab + (ar * ASTRIDE + ac * 8) * 2,                                 \
             A_ + (size_t)(m0 + ar) * DM + k0 + ac * 8);                       \
        cp16(ab + ((ar + 64) * ASTRIDE + ac * 8) * 2,                          \
             A_ + (size_t)(m0 + ar + 64) * DM + k0 + ac * 8);                  \
        cp16(bb + (br * BSTRIDE + bc * 8) * 2,                                 \
             W_ + (size_t)(k0 + br) * DM + n0 + bc * 8);                       \
        cp16(bb + ((br + 16) * BSTRIDE + bc * 8) * 2,                          \
             W_ + (size_t)(k0 + br + 16) * DM + n0 + bc * 8);                  \
        CP_COMMIT();                                                           \
    };                                                                         \
    issue(0, 0);                                                               \
    issue(1, 1);                                                               \
    issue(2, 2);                                                               \
    const int NT = DM / TBK;   /* 32 */                                        \
    for (int kt = 0; kt < NT; kt++) {                                          \
        const int s = kt & 3;                                                  \
        if (kt + 2 < NT)      { CP_WAIT2(); }                                  \
        else if (kt + 1 < NT) { CP_WAIT1(); }                                  \
        else                  { CP_WAIT0(); }                                  \
        __syncthreads();                                                       \
        if (kt + 3 < NT) issue(kt + 3, (kt + 3) & 3);                          \
        const uint32_t ab = sbase + s * STAGE_BYTES;                           \
        const uint32_t bb = ab + A_BYTES;                                      \
        _Pragma("unroll")                                                      \
        for (int ks = 0; ks < 2; ks++) {                                       \
            uint32_t af[4][4], bf[4][2];                                       \
            _Pragma("unroll")                                                  \
            for (int mf = 0; mf < 4; mf++)                                     \
                ldsm_x4(af[mf][0], af[mf][1], af[mf][2], af[mf][3],            \
                        ab + aoff[mf] + ks * 32);                              \
            ldsm_x4_t(bf[0][0], bf[0][1], bf[1][0], bf[1][1],                  \
                      bb + boff[0] + ks * (16 * BSTRIDE * 2));                 \
            ldsm_x4_t(bf[2][0], bf[2][1], bf[3][0], bf[3][1],                  \
                      bb + boff[1] + ks * (16 * BSTRIDE * 2));                 \
            _Pragma("unroll")                                                  \
            for (int mf = 0; mf < 4; mf++)                                     \
                _Pragma("unroll")                                              \
                for (int nf = 0; nf < 4; nf++)                                 \
                    mma_f16(acc[mf][nf][0], acc[mf][nf][1],                    \
                            acc[mf][nf][2], acc[mf][nf][3],                    \
                            af[mf][0], af[mf][1], af[mf][2], af[mf][3],        \
                            bf[nf][0], bf[nf][1]);                             \
        }                                                                      \
    }

// ============ QKV GEMM: fused RoPE epilogue =================================
__global__ __launch_bounds__(256) void gemm_qkv_kernel(const int* __restrict__ pos)
{
    const int z = blockIdx.z;
    const __half* __restrict__ W =
        (z == 0) ? g_Wqh : (z == 1) ? g_Wkh : g_Wvh;
    __half* __restrict__ dsth = (z == 0) ? g_Qh : (z == 1) ? g_Kh : g_Vh;
    const __half* __restrict__ A = g_xh;

    GEMM_BODY(A, W)

    const int rb = m0 + wm * 64 + lr;
    const int cb = n0 + wn * 32 + 2 * lc;

    float invf[4];
    #pragma unroll
    for (int nf = 0; nf < 4; nf++) {
        const int d = (cb + nf * 8) & 63;
        invf[nf] = 1.0f / powf(10000.0f, (float)d / 64.0f);
    }
    const float qscale = (z == 0) ? 0.125f : 1.0f;

    #pragma unroll
    for (int mf = 0; mf < 4; mf++) {
        #pragma unroll
        for (int half = 0; half < 2; half++) {
            const int m = rb + mf * 16 + half * 8;
            const int b_ = m >> 11, s_ = m & (SEQ - 1);
            const float p = (float)pos[b_ * SEQ + s_];
            #pragma unroll
            for (int nf = 0; nf < 4; nf++) {
                const int n = cb + nf * 8;
                const int h = n >> 6, d = n & 63;
                const float ve = acc[mf][nf][half * 2];
                const float vo = acc[mf][nf][half * 2 + 1];
                float re, ro;
                if (z < 2) {
                    float sn, cs;
                    sincosf(p * invf[nf], &sn, &cs);
                    re = (ve * cs - vo * sn) * qscale;
                    ro = (ve * sn + vo * cs) * qscale;
                } else {
                    re = ve; ro = vo;
                }
                __half2* dp = (__half2*)(dsth + (((size_t)(b_ * NH + h)) * SEQ + s_) * DK + d);
                *dp = __floats2half2_rn(re, ro);
            }
        }
    }
}

// ============ WO GEMM ========================================================
__global__ __launch_bounds__(256) void gemm_out_kernel(float* __restrict__ out)
{
    const __half* __restrict__ A = g_Oh;
    const __half* __restrict__ W = g_Woh;

    GEMM_BODY(A, W)

    const int rb = m0 + wm * 64 + lr;
    const int cb = n0 + wn * 32 + 2 * lc;
    #pragma unroll
    for (int mf = 0; mf < 4; mf++) {
        #pragma unroll
        for (int nf = 0; nf < 4; nf++) {
            const int n = cb + nf * 8;
            #pragma unroll
            for (int half = 0; half < 2; half++) {
                const int m = rb + mf * 16 + half * 8;
                *(float2*)(out + (size_t)m * DM + n) =
                    make_float2(acc[mf][nf][half * 2], acc[mf][nf][half * 2 + 1]);
            }
        }
    }
}

// ====== fp16 flash attention: cp.async 3-stage K/V, ldmatrix fragments ======
// CTA = 64 query rows, 4 warps x 16. KV tile = 64. Natural [j][d] layouts.
#define FBM 64
#define FBN 64
#define FSTR 72                         // halves per row (64 + 8 pad)
#define FQ_BYTES (64 * FSTR * 2)        // 9216
#define FK_BYTES (64 * FSTR * 2)        // 9216
#define FSTAGE_BYTES (2 * FK_BYTES)     // K + V = 18432
#define FLASH_SMEM (FQ_BYTES + 3 * FSTAGE_BYTES)   // 64512

__global__ __launch_bounds__(128, 3) void flash_f16_kernel()
{
    extern __shared__ __half fsh[];
    const uint32_t fbase = (uint32_t)__cvta_generic_to_shared(fsh);
    const uint32_t qb = fbase;

    const int bh = blockIdx.y;
    const int m0 = ((int)gridDim.x - 1 - (int)blockIdx.x) * FBM;  // heavy first
    const int tid  = threadIdx.x;
    const int lane = tid & 31;
    const int w    = tid >> 5;
    const int lr   = lane >> 2;
    const int lc   = lane & 3;
    const int q8 = lane >> 3, r8 = lane & 7;

    const __half* __restrict__ Qb = g_Qh + (size_t)bh * SEQ * DK;
    const __half* __restrict__ Kb = g_Kh + (size_t)bh * SEQ * DK;
    const __half* __restrict__ Vb = g_Vh + (size_t)bh * SEQ * DK;

    // per-thread copy coords: 512 chunks of 16B per 64x64 tile, 4 per thread
    const int crow = tid >> 1;                 // wrong granularity? see below
    (void)crow;

    // ldsm offsets
    // Q A-frag: rows w*16 + (q8&1)*8 + r8, col (q8>>1)*8  (+ks*16)
    const uint32_t qoff =
        ((w * 16 + (q8 & 1) * 8 + r8) * FSTR + (q8 >> 1) * 8) * 2;
    // K B-frag (non-trans): j = ((lane>>4)&1)*8 + (lane&7), d = ((lane>>3)&1)*8
    const uint32_t koff =
        ((((lane >> 4) & 1) * 8 + (lane & 7)) * FSTR + ((lane >> 3) & 1) * 8) * 2;
    // V B-frag (trans, GEMM boff pattern): row k=(q8&1)*8+r8, col (q8>>1)*8
    const uint32_t voff =
        (((q8 & 1) * 8 + r8) * FSTR + (q8 >> 1) * 8) * 2;

    // ---- stage Q via cp.async ----
    {
        #pragma unroll
        for (int it = 0; it < 4; it++) {
            const int idx = tid + it * 128;          // 0..511
            const int row = idx >> 3, ch = idx & 7;
            cp16(qb + (row * FSTR + ch * 8) * 2,
                 Qb + (size_t)(m0 + row) * DK + ch * 8);
        }
        CP_COMMIT();
    }

    auto issue_kv = [&](int t, int s) {
        const uint32_t kb = fbase + FQ_BYTES + s * FSTAGE_BYTES;
        const uint32_t vb = kb + FK_BYTES;
        const int j0 = t * FBN;
        #pragma unroll
        for (int it = 0; it < 4; it++) {
            const int idx = tid + it * 128;
            const int row = idx >> 3, ch = idx & 7;
            cp16(kb + (row * FSTR + ch * 8) * 2,
                 Kb + (size_t)(j0 + row) * DK + ch * 8);
            cp16(vb + (row * FSTR + ch * 8) * 2,
                 Vb + (size_t)(j0 + row) * DK + ch * 8);
        }
        CP_COMMIT();
    };

    const int nt = m0 / FBN + 1;
    issue_kv(0, 0);
    if (nt > 1) issue_kv(1, 1);

    // Q frags (Q group + up to 2 KV groups pending -> wait for Q done)
    uint32_t qf[4][4];
    {
        if (nt > 1) { CP_WAIT2(); } else { CP_WAIT1(); }
        __syncthreads();
        #pragma unroll
        for (int ks = 0; ks < 4; ks++)
            ldsm_x4(qf[ks][0], qf[ks][1], qf[ks][2], qf[ks][3],
                    qb + qoff + ks * 32);
    }

    float o[8][4];
    #pragma unroll
    for (int n = 0; n < 8; n++)
        #pragma unroll
        for (int c = 0; c < 4; c++) o[n][c] = 0.f;
    float mrow0 = -1e30f, mrow1 = -1e30f, lrow0 = 0.f, lrow1 = 0.f;

    for (int t = 0; t < nt; t++) {
        const int s = t % 3;
        // wait for tile t's KV (groups pending after it: t+1 if issued)
        if (t + 1 < nt) { CP_WAIT1(); } else { CP_WAIT0(); }
        __syncthreads();
        if (t + 2 < nt) issue_kv(t + 2, (t + 2) % 3);

        const uint32_t kb = fbase + FQ_BYTES + s * FSTAGE_BYTES;
        const uint32_t vb = kb + FK_BYTES;

        // ---- S = Q K^T ----
        float sacc[8][4];
        #pragma unroll
        for (int n = 0; n < 8; n++)
            #pragma unroll
            for (int c = 0; c < 4; c++) sacc[n][c] = 0.f;

        #pragma unroll
        for (int ks = 0; ks < 4; ks++) {
            #pragma unroll
            for (int jp = 0; jp < 4; jp++) {    // 16-j group
                uint32_t b0a, b1a, b0b, b1b;
                ldsm_x4(b0a, b1a, b0b, b1b,
                        kb + koff + (jp * 16 * FSTR + ks * 16) * 2);
                mma_f16(sacc[2*jp][0], sacc[2*jp][1], sacc[2*jp][2], sacc[2*jp][3],
                        qf[ks][0], qf[ks][1], qf[ks][2], qf[ks][3], b0a, b1a);
                mma_f16(sacc[2*jp+1][0], sacc[2*jp+1][1], sacc[2*jp+1][2], sacc[2*jp+1][3],
                        qf[ks][0], qf[ks][1], qf[ks][2], qf[ks][3], b0b, b1b);
            }
        }

        // ---- causal mask: diagonal tile only ----
        if (t == nt - 1) {
            const int r0 = w * 16 + lr;
            #pragma unroll
            for (int n = 0; n < 8; n++) {
                const int c0 = n * 8 + 2 * lc;
                if (c0     > r0)     sacc[n][0] = -1e30f;
                if (c0 + 1 > r0)     sacc[n][1] = -1e30f;
                if (c0     > r0 + 8) sacc[n][2] = -1e30f;
                if (c0 + 1 > r0 + 8) sacc[n][3] = -1e30f;
            }
        }

        // ---- online softmax ----
        float mx0 = -1e30f, mx1 = -1e30f;
        #pragma unroll
        for (int n = 0; n < 8; n++) {
            mx0 = fmaxf(mx0, fmaxf(sacc[n][0], sacc[n][1]));
            mx1 = fmaxf(mx1, fmaxf(sacc[n][2], sacc[n][3]));
        }
        mx0 = fmaxf(mx0, __shfl_xor_sync(0xffffffffu, mx0, 1));
        mx0 = fmaxf(mx0, __shfl_xor_sync(0xffffffffu, mx0, 2));
        mx1 = fmaxf(mx1, __shfl_xor_sync(0xffffffffu, mx1, 1));
        mx1 = fmaxf(mx1, __shfl_xor_sync(0xffffffffu, mx1, 2));

        const float mn0 = fmaxf(mrow0, mx0);
        const float mn1 = fmaxf(mrow1, mx1);
        const float sc0 = __expf(mrow0 - mn0);
        const float sc1 = __expf(mrow1 - mn1);
        lrow0 *= sc0; lrow1 *= sc1;
        #pragma unroll
        for (int n = 0; n < 8; n++) {
            o[n][0] *= sc0; o[n][1] *= sc0;
            o[n][2] *= sc1; o[n][3] *= sc1;
        }
        mrow0 = mn0; mrow1 = mn1;

        uint32_t pv[8][2];
        #pragma unroll
        for (int n = 0; n < 8; n++) {
            const float p0 = __expf(sacc[n][0] - mn0);
            const float p1 = __expf(sacc[n][1] - mn0);
            const float p2 = __expf(sacc[n][2] - mn1);
            const float p3 = __expf(sacc[n][3] - mn1);
            lrow0 += p0 + p1;
            lrow1 += p2 + p3;
            pv[n][0] = f2h2u(p0, p1);
            pv[n][1] = f2h2u(p2, p3);
        }

        // ---- O += P V ----
        #pragma unroll
        for (int ks = 0; ks < 4; ks++) {
            const uint32_t a0 = pv[2 * ks    ][0];
            const uint32_t a1 = pv[2 * ks    ][1];
            const uint32_t a2 = pv[2 * ks + 1][0];
            const uint32_t a3 = pv[2 * ks + 1][1];
            #pragma unroll
            for (int np = 0; np < 2; np++) {    // 32-d halves (2 x4_t loads)
                uint32_t b0a, b1a, b0b, b1b;
                ldsm_x4_t(b0a, b1a, b0b, b1b,
                          vb + voff + (ks * 16 * FSTR + np * 32) * 2);
                mma_f16(o[4*np  ][0], o[4*np  ][1], o[4*np  ][2], o[4*np  ][3],
                        a0, a1, a2, a3, b0a, b1a);
                mma_f16(o[4*np+1][0], o[4*np+1][1], o[4*np+1][2], o[4*np+1][3],
                        a0, a1, a2, a3, b0b, b1b);
                uint32_t c0a, c1a, c0b, c1b;
                ldsm_x4_t(c0a, c1a, c0b, c1b,
                          vb + voff + (ks * 16 * FSTR + np * 32 + 16) * 2);
                mma_f16(o[4*np+2][0], o[4*np+2][1], o[4*np+2][2], o[4*np+2][3],
                        a0, a1, a2, a3, c0a, c1a);
                mma_f16(o[4*np+3][0], o[4*np+3][1], o[4*np+3][2], o[4*np+3][3],
                        a0, a1, a2, a3, c0b, c1b);
            }
        }
        __syncthreads();   // all warps done with stage s before overwrite
    }

    lrow0 += __shfl_xor_sync(0xffffffffu, lrow0, 1);
    lrow0 += __shfl_xor_sync(0xffffffffu, lrow0, 2);
    lrow1 += __shfl_xor_sync(0xffffffffu, lrow1, 1);
    lrow1 += __shfl_xor_sync(0xffffffffu, lrow1, 2);
    const float inv0 = 1.0f / lrow0;
    const float inv1 = 1.0f / lrow1;

    const int b_ = bh >> 4, h = bh & 15;
    const int r0 = m0 + w * 16 + lr;
    const int r1 = r0 + 8;
    #pragma unroll
    for (int n = 0; n < 8; n++) {
        const int d = h * 64 + n * 8 + 2 * lc;
        *(__half2*)(g_Oh + ((size_t)b_ * SEQ + r0) * DM + d) =
            __floats2half2_rn(o[n][0] * inv0, o[n][1] * inv0);
        *(__half2*)(g_Oh + ((size_t)b_ * SEQ + r1) * DM + d) =
            __floats2half2_rn(o[n][2] * inv1, o[n][3] * inv1);
    }
}

// ---------------- launch ----------------------------------------------------
extern "C" void kernel_launch(void* const* d_in, const int* in_sizes, int n_in,
                              void* d_out, int out_size)
{
    (void)in_sizes; (void)n_in; (void)out_size;
    const float* x   = (const float*)d_in[0];
    const int*   pos = (const int*)  d_in[1];
    const float* WQ  = (const float*)d_in[2];
    const float* WK  = (const float*)d_in[3];
    const float* WV  = (const float*)d_in[4];
    const float* WO  = (const float*)d_in[5];
    float* out = (float*)d_out;

    cudaFuncSetAttribute(gemm_qkv_kernel,
                         cudaFuncAttributeMaxDynamicSharedMemorySize, GEMM_SMEM);
    cudaFuncSetAttribute(gemm_out_kernel,
                         cudaFuncAttributeMaxDynamicSharedMemorySize, GEMM_SMEM);
    cudaFuncSetAttribute(flash_f16_kernel,
                         cudaFuncAttributeMaxDynamicSharedMemorySize, FLASH_SMEM);

    const int ncvt = (NX + 4 * NW) / (8 * 256);
    cvt_kernel<<<ncvt, 256>>>(x, WQ, WK, WV, WO);

    dim3 gq(DM / TBN, (BATCH * SEQ) / TBM, 3);      // (8, 32, 3)
    gemm_qkv_kernel<<<gq, 256, GEMM_SMEM>>>(pos);

    dim3 gf(SEQ / FBM, BATCH * NH);                 // (32, 32)
    flash_f16_kernel<<<gf, 128, FLASH_SMEM>>>();

    dim3 go(DM / TBN, (BATCH * SEQ) / TBM, 1);      // (8, 32)
    gemm_out_kernel<<<go, 256, GEMM_SMEM>>>(out);
}